// round 2
// baseline (speedup 1.0000x reference)
#include <cuda_runtime.h>
#include <cstdint>

#define N_NODES 50000
#define N_EDGES 1600000
#define IN_F    256
#define HID_F   128
#define OUT_F   40

// ---------------- scratch (device globals; no allocs allowed) ----------------
__device__ int   g_is64;
__device__ int   g_degc[N_NODES];
__device__ float g_dinv[N_NODES];
__device__ int   g_off[N_NODES + 1];
__device__ int   g_cursor[N_NODES];
__device__ int   g_csrc[N_EDGES];
__device__ float g_cnorm[N_EDGES];
__device__ __align__(16) float g_hw [N_NODES * HID_F];
__device__ __align__(16) float g_agg[N_NODES * HID_F];

// ---------------- dtype detection: int64 vs int32 edge_index ----------------
// If edge_index is little-endian int64 with values < 2^31, every odd int32 word
// is zero. For int32 data (random ids in [0, 50000)), 512 consecutive odd words
// all being zero is impossible in practice.
__global__ void detect_kernel(const int* __restrict__ ei32) {
    if (threadIdx.x == 0 && blockIdx.x == 0) {
        int ok = 1;
        #pragma unroll 1
        for (int i = 0; i < 512; i++) {
            if (ei32[2 * i + 1] != 0) { ok = 0; break; }
        }
        g_is64 = ok;
    }
}

__device__ __forceinline__ int load_id(const void* ei, int idx) {
    if (g_is64) return (int)((const long long*)ei)[idx];
    return ((const int*)ei)[idx];
}

// ---------------- small prep kernels ----------------
__global__ void zero_deg_kernel() {
    int i = blockIdx.x * blockDim.x + threadIdx.x;
    if (i < N_NODES) g_degc[i] = 0;
}

__global__ void deg_kernel(const void* __restrict__ ei) {
    int e = blockIdx.x * blockDim.x + threadIdx.x;
    if (e < N_EDGES) {
        int d = load_id(ei, N_EDGES + e);
        if ((unsigned)d < (unsigned)N_NODES) atomicAdd(&g_degc[d], 1);
    }
}

__global__ void dinv_kernel() {
    int i = blockIdx.x * blockDim.x + threadIdx.x;
    if (i < N_NODES) g_dinv[i] = rsqrtf((float)g_degc[i] + 1.0f);  // +1 self-loop
}

// single-block exclusive scan over g_degc -> g_off, g_cursor
__global__ void scan_kernel() {
    __shared__ int warp_sums[32];
    __shared__ int s_carry;
    int t = threadIdx.x, lane = t & 31, wid = t >> 5;
    if (t == 0) s_carry = 0;
    __syncthreads();
    for (int base = 0; base < N_NODES; base += 1024) {
        int i = base + t;
        int v = (i < N_NODES) ? g_degc[i] : 0;
        int x = v;
        #pragma unroll
        for (int o = 1; o < 32; o <<= 1) {
            int y = __shfl_up_sync(0xFFFFFFFFu, x, o);
            if (lane >= o) x += y;
        }
        if (lane == 31) warp_sums[wid] = x;
        __syncthreads();
        if (wid == 0) {
            int s = warp_sums[lane];
            #pragma unroll
            for (int o = 1; o < 32; o <<= 1) {
                int y = __shfl_up_sync(0xFFFFFFFFu, s, o);
                if (lane >= o) s += y;
            }
            warp_sums[lane] = s;
        }
        __syncthreads();
        int warp_excl = (wid == 0) ? 0 : warp_sums[wid - 1];
        int incl = x + warp_excl + s_carry;
        int excl = incl - v;
        if (i < N_NODES) { g_off[i] = excl; g_cursor[i] = excl; }
        __syncthreads();
        if (t == 1023) s_carry = incl;
        __syncthreads();
    }
    if (threadIdx.x == 0) g_off[N_NODES] = s_carry;
}

__global__ void fill_kernel(const void* __restrict__ ei) {
    int e = blockIdx.x * blockDim.x + threadIdx.x;
    if (e < N_EDGES) {
        int s = load_id(ei, e);
        int d = load_id(ei, N_EDGES + e);
        if ((unsigned)s < (unsigned)N_NODES && (unsigned)d < (unsigned)N_NODES) {
            int pos = atomicAdd(&g_cursor[d], 1);
            g_csrc[pos] = s;
            g_cnorm[pos] = g_dinv[s] * g_dinv[d];
        }
    }
}

// ---------------- SGEMM: g_hw[M,N] = op(A)[M,K] * B[K,N], op = optional relu ----
// a_sel: 0 -> external pointer A_ext (input x), 1 -> g_agg
__global__ __launch_bounds__(256) void sgemm_kernel(
    const float* __restrict__ A_ext, const float* __restrict__ B,
    int M, int K, int N, int reluA, int a_sel)
{
    const float* A = a_sel ? (const float*)g_agg : A_ext;
    float* C = g_hw;
    const int BM = 64, BN = 64, BK = 16, TM = 4, TN = 4;
    __shared__ float As[BK][BM + 1];
    __shared__ float Bs[BK][BN];
    int block_row = blockIdx.y * BM;
    int block_col = blockIdx.x * BN;
    int tid = threadIdx.x;
    int tr = tid / 16, tc = tid % 16;
    float acc[TM][TN] = {};
    for (int k0 = 0; k0 < K; k0 += BK) {
        #pragma unroll
        for (int i = tid; i < BM * BK; i += 256) {
            int m = i / BK, k = i % BK;
            int gm = block_row + m;
            float v = (gm < M) ? A[(size_t)gm * K + k0 + k] : 0.0f;
            if (reluA) v = fmaxf(v, 0.0f);
            As[k][m] = v;
        }
        #pragma unroll
        for (int i = tid; i < BK * BN; i += 256) {
            int k = i / BN, n = i % BN;
            int gn = block_col + n;
            Bs[k][n] = (gn < N) ? B[(size_t)(k0 + k) * N + gn] : 0.0f;
        }
        __syncthreads();
        #pragma unroll
        for (int k = 0; k < BK; k++) {
            float a[TM], b[TN];
            #pragma unroll
            for (int i = 0; i < TM; i++) a[i] = As[k][tr * TM + i];
            #pragma unroll
            for (int j = 0; j < TN; j++) b[j] = Bs[k][tc * TN + j];
            #pragma unroll
            for (int i = 0; i < TM; i++)
                #pragma unroll
                for (int j = 0; j < TN; j++)
                    acc[i][j] += a[i] * b[j];
        }
        __syncthreads();
    }
    #pragma unroll
    for (int i = 0; i < TM; i++) {
        int gm = block_row + tr * TM + i;
        if (gm >= M) continue;
        #pragma unroll
        for (int j = 0; j < TN; j++) {
            int gn = block_col + tc * TN + j;
            if (gn < N) C[(size_t)gm * N + gn] = acc[i][j];
        }
    }
}

// ---------------- aggregation: warp per node, fused self-loop + bias ----------
// reads g_hw; out_sel: 1 -> g_agg, 0 -> external out pointer
__global__ __launch_bounds__(256) void aggregate_kernel(
    const float* __restrict__ bias, float* __restrict__ out_ext, int F, int out_sel)
{
    float* out = out_sel ? (float*)g_agg : out_ext;
    int warp = (blockIdx.x * blockDim.x + threadIdx.x) >> 5;
    int lane = threadIdx.x & 31;
    if (warp >= N_NODES) return;
    int F4 = F >> 2;
    bool active = lane < F4;
    const float4* HW = (const float4*)g_hw;
    int beg = g_off[warp], end = g_off[warp + 1];
    float4 acc = make_float4(0.f, 0.f, 0.f, 0.f);

    int j = beg;
    for (; j + 4 <= end; j += 4) {
        int   s0 = g_csrc[j],     s1 = g_csrc[j + 1], s2 = g_csrc[j + 2], s3 = g_csrc[j + 3];
        float w0 = g_cnorm[j],    w1 = g_cnorm[j + 1], w2 = g_cnorm[j + 2], w3 = g_cnorm[j + 3];
        if (active) {
            float4 v0 = HW[(size_t)s0 * F4 + lane];
            float4 v1 = HW[(size_t)s1 * F4 + lane];
            float4 v2 = HW[(size_t)s2 * F4 + lane];
            float4 v3 = HW[(size_t)s3 * F4 + lane];
            acc.x += w0 * v0.x; acc.y += w0 * v0.y; acc.z += w0 * v0.z; acc.w += w0 * v0.w;
            acc.x += w1 * v1.x; acc.y += w1 * v1.y; acc.z += w1 * v1.z; acc.w += w1 * v1.w;
            acc.x += w2 * v2.x; acc.y += w2 * v2.y; acc.z += w2 * v2.z; acc.w += w2 * v2.w;
            acc.x += w3 * v3.x; acc.y += w3 * v3.y; acc.z += w3 * v3.z; acc.w += w3 * v3.w;
        }
    }
    for (; j < end; j++) {
        int s = g_csrc[j];
        float w = g_cnorm[j];
        if (active) {
            float4 v = HW[(size_t)s * F4 + lane];
            acc.x += w * v.x; acc.y += w * v.y; acc.z += w * v.z; acc.w += w * v.w;
        }
    }
    if (active) {
        float di = g_dinv[warp];
        float sw = di * di;
        float4 v = HW[(size_t)warp * F4 + lane];
        float4 b4 = ((const float4*)bias)[lane];
        acc.x += sw * v.x + b4.x;
        acc.y += sw * v.y + b4.y;
        acc.z += sw * v.z + b4.z;
        acc.w += sw * v.w + b4.w;
        ((float4*)out)[(size_t)warp * F4 + lane] = acc;
    }
}

// ---------------- log_softmax over 40 cols, warp per row, in-place ----------------
__global__ __launch_bounds__(256) void logsoftmax_kernel(float* __restrict__ out) {
    int row = (blockIdx.x * blockDim.x + threadIdx.x) >> 5;
    int lane = threadIdx.x & 31;
    if (row >= N_NODES) return;
    float* p = out + (size_t)row * OUT_F;
    float x1 = p[lane];
    float x2 = (lane < OUT_F - 32) ? p[32 + lane] : -3.4e38f;
    float m = fmaxf(x1, x2);
    #pragma unroll
    for (int o = 16; o > 0; o >>= 1) m = fmaxf(m, __shfl_xor_sync(0xFFFFFFFFu, m, o));
    float s = __expf(x1 - m) + ((lane < OUT_F - 32) ? __expf(x2 - m) : 0.0f);
    #pragma unroll
    for (int o = 16; o > 0; o >>= 1) s += __shfl_xor_sync(0xFFFFFFFFu, s, o);
    float lse = m + __logf(s);
    p[lane] = x1 - lse;
    if (lane < OUT_F - 32) p[32 + lane] = x2 - lse;
}

// ---------------- launch ----------------
extern "C" void kernel_launch(void* const* d_in, const int* in_sizes, int n_in,
                              void* d_out, int out_size)
{
    const float* x  = (const float*)d_in[0];
    const void*  ei = d_in[1];
    const float* W1 = (const float*)d_in[2];
    const float* b1 = (const float*)d_in[3];
    const float* W2 = (const float*)d_in[4];
    const float* b2 = (const float*)d_in[5];
    const float* W3 = (const float*)d_in[6];
    const float* b3 = (const float*)d_in[7];
    float* out = (float*)d_out;

    const int TB = 256;
    // CSR build
    detect_kernel<<<1, 32>>>((const int*)ei);
    zero_deg_kernel<<<(N_NODES + TB - 1) / TB, TB>>>();
    deg_kernel<<<(N_EDGES + TB - 1) / TB, TB>>>(ei);
    dinv_kernel<<<(N_NODES + TB - 1) / TB, TB>>>();
    scan_kernel<<<1, 1024>>>();
    fill_kernel<<<(N_EDGES + TB - 1) / TB, TB>>>(ei);

    int agg_grid = (N_NODES * 32 + TB - 1) / TB;

    // layer 1: hw = x @ W1 ; agg = A_norm*hw + b1  (relu deferred to next gemm load)
    {
        dim3 grid((HID_F + 63) / 64, (N_NODES + 63) / 64);
        sgemm_kernel<<<grid, 256>>>(x, W1, N_NODES, IN_F, HID_F, 0, 0);
        aggregate_kernel<<<agg_grid, TB>>>(b1, nullptr, HID_F, 1);
    }
    // layer 2
    {
        dim3 grid((HID_F + 63) / 64, (N_NODES + 63) / 64);
        sgemm_kernel<<<grid, 256>>>(x, W2, N_NODES, HID_F, HID_F, 1, 1);
        aggregate_kernel<<<agg_grid, TB>>>(b2, nullptr, HID_F, 1);
    }
    // layer 3 (output into d_out) + log_softmax
    {
        dim3 grid((OUT_F + 63) / 64, (N_NODES + 63) / 64);
        sgemm_kernel<<<grid, 256>>>(x, W3, N_NODES, HID_F, OUT_F, 1, 1);
        aggregate_kernel<<<agg_grid, TB>>>(b3, out, OUT_F, 0);
        logsoftmax_kernel<<<agg_grid, TB>>>(out);
    }
}

// round 3
// speedup vs baseline: 1.0082x; 1.0082x over previous
#include <cuda_runtime.h>
#include <cstdint>

#define N_NODES 50000
#define N_EDGES 1600000
#define IN_F    256
#define HID_F   128
#define OUT_F   40

// ---------------- scratch (device globals; no allocs allowed) ----------------
__device__ int   g_is64;
__device__ int   g_degc[N_NODES];
__device__ float g_dinv[N_NODES];
__device__ int   g_off[N_NODES + 1];
__device__ int   g_cursor[N_NODES];
__device__ int   g_csrc[N_EDGES];
__device__ float g_cnorm[N_EDGES];
__device__ __align__(16) float g_hw [N_NODES * HID_F];
__device__ __align__(16) float g_agg[N_NODES * HID_F];

// ---------------- dtype detection: int64 vs int32 edge_index ----------------
__global__ void detect_kernel(const int* __restrict__ ei32) {
    if (threadIdx.x == 0 && blockIdx.x == 0) {
        int ok = 1;
        #pragma unroll 1
        for (int i = 0; i < 512; i++) {
            if (ei32[2 * i + 1] != 0) { ok = 0; break; }
        }
        g_is64 = ok;
    }
}

__device__ __forceinline__ int load_id(const void* ei, int idx) {
    if (g_is64) return (int)((const long long*)ei)[idx];
    return ((const int*)ei)[idx];
}

// ---------------- small prep kernels ----------------
__global__ void zero_deg_kernel() {
    int i = blockIdx.x * blockDim.x + threadIdx.x;
    if (i < N_NODES) g_degc[i] = 0;
}

__global__ void deg_kernel(const void* __restrict__ ei) {
    int e = blockIdx.x * blockDim.x + threadIdx.x;
    if (e < N_EDGES) {
        int d = load_id(ei, N_EDGES + e);
        if ((unsigned)d < (unsigned)N_NODES) atomicAdd(&g_degc[d], 1);
    }
}

__global__ void dinv_kernel() {
    int i = blockIdx.x * blockDim.x + threadIdx.x;
    if (i < N_NODES) g_dinv[i] = rsqrtf((float)g_degc[i] + 1.0f);  // +1 self-loop
}

// single-block exclusive scan over g_degc -> g_off, g_cursor
__global__ void scan_kernel() {
    __shared__ int warp_sums[32];
    __shared__ int s_carry;
    int t = threadIdx.x, lane = t & 31, wid = t >> 5;
    if (t == 0) s_carry = 0;
    __syncthreads();
    for (int base = 0; base < N_NODES; base += 1024) {
        int i = base + t;
        int v = (i < N_NODES) ? g_degc[i] : 0;
        int x = v;
        #pragma unroll
        for (int o = 1; o < 32; o <<= 1) {
            int y = __shfl_up_sync(0xFFFFFFFFu, x, o);
            if (lane >= o) x += y;
        }
        if (lane == 31) warp_sums[wid] = x;
        __syncthreads();
        if (wid == 0) {
            int s = warp_sums[lane];
            #pragma unroll
            for (int o = 1; o < 32; o <<= 1) {
                int y = __shfl_up_sync(0xFFFFFFFFu, s, o);
                if (lane >= o) s += y;
            }
            warp_sums[lane] = s;
        }
        __syncthreads();
        int warp_excl = (wid == 0) ? 0 : warp_sums[wid - 1];
        int incl = x + warp_excl + s_carry;
        int excl = incl - v;
        if (i < N_NODES) { g_off[i] = excl; g_cursor[i] = excl; }
        __syncthreads();
        if (t == 1023) s_carry = incl;
        __syncthreads();
    }
    if (threadIdx.x == 0) g_off[N_NODES] = s_carry;
}

__global__ void fill_kernel(const void* __restrict__ ei) {
    int e = blockIdx.x * blockDim.x + threadIdx.x;
    if (e < N_EDGES) {
        int s = load_id(ei, e);
        int d = load_id(ei, N_EDGES + e);
        if ((unsigned)s < (unsigned)N_NODES && (unsigned)d < (unsigned)N_NODES) {
            int pos = atomicAdd(&g_cursor[d], 1);
            g_csrc[pos] = s;
            g_cnorm[pos] = g_dinv[s] * g_dinv[d];
        }
    }
}

// ---------------- specialized SGEMM for N=128: g_hw = op(A)[M,K] @ B[K,128] ----
// 128x128 tile, BK=8, 256 threads, 8x8 per-thread microtile, float4 everywhere.
// a_sel: 0 -> A_ext (input x), 1 -> g_agg
__global__ __launch_bounds__(256) void sgemm128_kernel(
    const float* __restrict__ A_ext, const float* __restrict__ B,
    int M, int K, int reluA, int a_sel)
{
    const float* A = a_sel ? (const float*)g_agg : A_ext;
    float* C = g_hw;
    __shared__ float As[8][128];
    __shared__ float Bs[8][128];

    int tid = threadIdx.x;
    int block_row = blockIdx.x * 128;
    int tr = tid >> 4;          // 0..15
    int tc = tid & 15;          // 0..15

    // A-load mapping: thread -> (m = tid/2, kq = (tid&1)*4)
    int lam = tid >> 1;
    int lak = (tid & 1) << 2;
    int gm_a = block_row + lam;
    // B-load mapping: thread -> (kb = tid/32, nq = (tid&31)*4)
    int lbk = tid >> 5;
    int lbn = (tid & 31) << 2;

    float acc[8][8] = {};

    for (int k0 = 0; k0 < K; k0 += 8) {
        float4 av = make_float4(0.f, 0.f, 0.f, 0.f);
        if (gm_a < M) av = *(const float4*)&A[(size_t)gm_a * K + k0 + lak];
        if (reluA) {
            av.x = fmaxf(av.x, 0.f); av.y = fmaxf(av.y, 0.f);
            av.z = fmaxf(av.z, 0.f); av.w = fmaxf(av.w, 0.f);
        }
        float4 bv = *(const float4*)&B[(size_t)(k0 + lbk) * 128 + lbn];
        As[lak + 0][lam] = av.x;
        As[lak + 1][lam] = av.y;
        As[lak + 2][lam] = av.z;
        As[lak + 3][lam] = av.w;
        *(float4*)&Bs[lbk][lbn] = bv;
        __syncthreads();

        #pragma unroll
        for (int k = 0; k < 8; k++) {
            float4 a0 = *(const float4*)&As[k][tr * 8];
            float4 a1 = *(const float4*)&As[k][tr * 8 + 4];
            float4 b0 = *(const float4*)&Bs[k][tc * 8];
            float4 b1 = *(const float4*)&Bs[k][tc * 8 + 4];
            float ar[8] = {a0.x, a0.y, a0.z, a0.w, a1.x, a1.y, a1.z, a1.w};
            float br[8] = {b0.x, b0.y, b0.z, b0.w, b1.x, b1.y, b1.z, b1.w};
            #pragma unroll
            for (int i = 0; i < 8; i++)
                #pragma unroll
                for (int j = 0; j < 8; j++)
                    acc[i][j] += ar[i] * br[j];
        }
        __syncthreads();
    }

    #pragma unroll
    for (int i = 0; i < 8; i++) {
        int gm = block_row + tr * 8 + i;
        if (gm >= M) continue;
        float4 c0 = make_float4(acc[i][0], acc[i][1], acc[i][2], acc[i][3]);
        float4 c1 = make_float4(acc[i][4], acc[i][5], acc[i][6], acc[i][7]);
        *(float4*)&C[(size_t)gm * 128 + tc * 8]     = c0;
        *(float4*)&C[(size_t)gm * 128 + tc * 8 + 4] = c1;
    }
}

// ---------------- generic SGEMM (used for layer 3, N=40) ----------------
__global__ __launch_bounds__(256) void sgemm_kernel(
    const float* __restrict__ A_ext, const float* __restrict__ B,
    int M, int K, int N, int reluA, int a_sel)
{
    const float* A = a_sel ? (const float*)g_agg : A_ext;
    float* C = g_hw;
    const int BM = 64, BN = 64, BK = 16, TM = 4, TN = 4;
    __shared__ float As[BK][BM + 1];
    __shared__ float Bs[BK][BN];
    int block_row = blockIdx.y * BM;
    int block_col = blockIdx.x * BN;
    int tid = threadIdx.x;
    int tr = tid / 16, tc = tid % 16;
    float acc[TM][TN] = {};
    for (int k0 = 0; k0 < K; k0 += BK) {
        #pragma unroll
        for (int i = tid; i < BM * BK; i += 256) {
            int m = i / BK, k = i % BK;
            int gm = block_row + m;
            float v = (gm < M) ? A[(size_t)gm * K + k0 + k] : 0.0f;
            if (reluA) v = fmaxf(v, 0.0f);
            As[k][m] = v;
        }
        #pragma unroll
        for (int i = tid; i < BK * BN; i += 256) {
            int k = i / BN, n = i % BN;
            int gn = block_col + n;
            Bs[k][n] = (gn < N) ? B[(size_t)(k0 + k) * N + gn] : 0.0f;
        }
        __syncthreads();
        #pragma unroll
        for (int k = 0; k < BK; k++) {
            float a[TM], b[TN];
            #pragma unroll
            for (int i = 0; i < TM; i++) a[i] = As[k][tr * TM + i];
            #pragma unroll
            for (int j = 0; j < TN; j++) b[j] = Bs[k][tc * TN + j];
            #pragma unroll
            for (int i = 0; i < TM; i++)
                #pragma unroll
                for (int j = 0; j < TN; j++)
                    acc[i][j] += a[i] * b[j];
        }
        __syncthreads();
    }
    #pragma unroll
    for (int i = 0; i < TM; i++) {
        int gm = block_row + tr * TM + i;
        if (gm >= M) continue;
        #pragma unroll
        for (int j = 0; j < TN; j++) {
            int gn = block_col + tc * TN + j;
            if (gn < N) C[(size_t)gm * N + gn] = acc[i][j];
        }
    }
}

// ---------------- aggregation: warp per node, fused self-loop + bias ----------
// reads g_hw; out_sel: 1 -> g_agg, 0 -> external out pointer
__global__ __launch_bounds__(256) void aggregate_kernel(
    const float* __restrict__ bias, float* __restrict__ out_ext, int F, int out_sel)
{
    float* out = out_sel ? (float*)g_agg : out_ext;
    int warp = (blockIdx.x * blockDim.x + threadIdx.x) >> 5;
    int lane = threadIdx.x & 31;
    if (warp >= N_NODES) return;
    int F4 = F >> 2;
    bool active = lane < F4;
    const float4* HW = (const float4*)g_hw;
    int beg = g_off[warp], end = g_off[warp + 1];
    float4 acc = make_float4(0.f, 0.f, 0.f, 0.f);

    int j = beg;
    for (; j + 4 <= end; j += 4) {
        int   s0 = g_csrc[j],     s1 = g_csrc[j + 1], s2 = g_csrc[j + 2], s3 = g_csrc[j + 3];
        float w0 = g_cnorm[j],    w1 = g_cnorm[j + 1], w2 = g_cnorm[j + 2], w3 = g_cnorm[j + 3];
        if (active) {
            float4 v0 = HW[(size_t)s0 * F4 + lane];
            float4 v1 = HW[(size_t)s1 * F4 + lane];
            float4 v2 = HW[(size_t)s2 * F4 + lane];
            float4 v3 = HW[(size_t)s3 * F4 + lane];
            acc.x += w0 * v0.x; acc.y += w0 * v0.y; acc.z += w0 * v0.z; acc.w += w0 * v0.w;
            acc.x += w1 * v1.x; acc.y += w1 * v1.y; acc.z += w1 * v1.z; acc.w += w1 * v1.w;
            acc.x += w2 * v2.x; acc.y += w2 * v2.y; acc.z += w2 * v2.z; acc.w += w2 * v2.w;
            acc.x += w3 * v3.x; acc.y += w3 * v3.y; acc.z += w3 * v3.z; acc.w += w3 * v3.w;
        }
    }
    for (; j < end; j++) {
        int s = g_csrc[j];
        float w = g_cnorm[j];
        if (active) {
            float4 v = HW[(size_t)s * F4 + lane];
            acc.x += w * v.x; acc.y += w * v.y; acc.z += w * v.z; acc.w += w * v.w;
        }
    }
    if (active) {
        float di = g_dinv[warp];
        float sw = di * di;
        float4 v = HW[(size_t)warp * F4 + lane];
        float4 b4 = ((const float4*)bias)[lane];
        acc.x += sw * v.x + b4.x;
        acc.y += sw * v.y + b4.y;
        acc.z += sw * v.z + b4.z;
        acc.w += sw * v.w + b4.w;
        ((float4*)out)[(size_t)warp * F4 + lane] = acc;
    }
}

// ---------------- log_softmax over 40 cols, warp per row, in-place ----------------
__global__ __launch_bounds__(256) void logsoftmax_kernel(float* __restrict__ out) {
    int row = (blockIdx.x * blockDim.x + threadIdx.x) >> 5;
    int lane = threadIdx.x & 31;
    if (row >= N_NODES) return;
    float* p = out + (size_t)row * OUT_F;
    float x1 = p[lane];
    float x2 = (lane < OUT_F - 32) ? p[32 + lane] : -3.4e38f;
    float m = fmaxf(x1, x2);
    #pragma unroll
    for (int o = 16; o > 0; o >>= 1) m = fmaxf(m, __shfl_xor_sync(0xFFFFFFFFu, m, o));
    float s = __expf(x1 - m) + ((lane < OUT_F - 32) ? __expf(x2 - m) : 0.0f);
    #pragma unroll
    for (int o = 16; o > 0; o >>= 1) s += __shfl_xor_sync(0xFFFFFFFFu, s, o);
    float lse = m + __logf(s);
    p[lane] = x1 - lse;
    if (lane < OUT_F - 32) p[32 + lane] = x2 - lse;
}

// ---------------- launch ----------------
extern "C" void kernel_launch(void* const* d_in, const int* in_sizes, int n_in,
                              void* d_out, int out_size)
{
    const float* x  = (const float*)d_in[0];
    const void*  ei = d_in[1];
    const float* W1 = (const float*)d_in[2];
    const float* b1 = (const float*)d_in[3];
    const float* W2 = (const float*)d_in[4];
    const float* b2 = (const float*)d_in[5];
    const float* W3 = (const float*)d_in[6];
    const float* b3 = (const float*)d_in[7];
    float* out = (float*)d_out;

    const int TB = 256;
    // CSR build
    detect_kernel<<<1, 32>>>((const int*)ei);
    zero_deg_kernel<<<(N_NODES + TB - 1) / TB, TB>>>();
    deg_kernel<<<(N_EDGES + TB - 1) / TB, TB>>>(ei);
    dinv_kernel<<<(N_NODES + TB - 1) / TB, TB>>>();
    scan_kernel<<<1, 1024>>>();
    fill_kernel<<<(N_EDGES + TB - 1) / TB, TB>>>(ei);

    int agg_grid = (N_NODES * 32 + TB - 1) / TB;
    int gemm128_grid = (N_NODES + 127) / 128;

    // layer 1: hw = x @ W1 ; agg = A_norm*hw + b1  (relu deferred to next gemm load)
    sgemm128_kernel<<<gemm128_grid, 256>>>(x, W1, N_NODES, IN_F, 0, 0);
    aggregate_kernel<<<agg_grid, TB>>>(b1, nullptr, HID_F, 1);

    // layer 2
    sgemm128_kernel<<<gemm128_grid, 256>>>(x, W2, N_NODES, HID_F, 1, 1);
    aggregate_kernel<<<agg_grid, TB>>>(b2, nullptr, HID_F, 1);

    // layer 3 (output into d_out) + log_softmax
    {
        dim3 grid((OUT_F + 63) / 64, (N_NODES + 63) / 64);
        sgemm_kernel<<<grid, 256>>>(x, W3, N_NODES, HID_F, OUT_F, 1, 1);
        aggregate_kernel<<<agg_grid, TB>>>(b3, out, OUT_F, 0);
        logsoftmax_kernel<<<agg_grid, TB>>>(out);
    }
}

// round 5
// speedup vs baseline: 1.1047x; 1.0957x over previous
#include <cuda_runtime.h>
#include <cstdint>

#define N_NODES 50000
#define N_EDGES 1600000
#define IN_F    256
#define HID_F   128
#define OUT_F   40
#define SCAN_B  256
#define N_BLKS  ((N_NODES + SCAN_B - 1) / SCAN_B)   // 196

// ---------------- scratch (device globals; no allocs allowed) ----------------
__device__ int   g_is64;
__device__ int   g_degc[N_NODES];
__device__ float g_dinv[N_NODES];
__device__ int   g_off[N_NODES + 1];
__device__ int   g_cursor[N_NODES];
__device__ int   g_bsum[N_BLKS];
__device__ int   g_csrc[N_EDGES];
__device__ float g_cnorm[N_EDGES];
__device__ __align__(16) float g_hw [N_NODES * HID_F];
__device__ __align__(16) float g_agg[N_NODES * HID_F];

// ---------------- dtype detection: int64 vs int32 edge_index ----------------
__global__ void detect_kernel(const int* __restrict__ ei32) {
    if (threadIdx.x == 0 && blockIdx.x == 0) {
        int ok = 1;
        #pragma unroll 1
        for (int i = 0; i < 512; i++) {
            if (ei32[2 * i + 1] != 0) { ok = 0; break; }
        }
        g_is64 = ok;
    }
}

__device__ __forceinline__ int load_id(const void* ei, int idx) {
    if (g_is64) return (int)((const long long*)ei)[idx];
    return ((const int*)ei)[idx];
}

// ---------------- small prep kernels ----------------
__global__ void zero_deg_kernel() {
    int i = blockIdx.x * blockDim.x + threadIdx.x;
    if (i < N_NODES) g_degc[i] = 0;
}

__global__ void deg_kernel(const void* __restrict__ ei) {
    int e = blockIdx.x * blockDim.x + threadIdx.x;
    if (e < N_EDGES) {
        int d = load_id(ei, N_EDGES + e);
        if ((unsigned)d < (unsigned)N_NODES) atomicAdd(&g_degc[d], 1);
    }
}

// ---------------- 3-phase parallel exclusive scan over g_degc ----------------
// phase 1: per-block (256-elem) local exclusive scan -> g_off, block totals -> g_bsum.
// Also computes g_dinv (reads degc anyway).
__global__ __launch_bounds__(SCAN_B) void scan_p1_kernel() {
    __shared__ int s_ws[8];
    int t = threadIdx.x, lane = t & 31, w = t >> 5;
    int i = blockIdx.x * SCAN_B + t;
    int v = (i < N_NODES) ? g_degc[i] : 0;
    if (i < N_NODES) g_dinv[i] = rsqrtf((float)v + 1.0f);   // +1 self-loop
    int x = v;
    #pragma unroll
    for (int o = 1; o < 32; o <<= 1) {
        int y = __shfl_up_sync(0xFFFFFFFFu, x, o);
        if (lane >= o) x += y;
    }
    if (lane == 31) s_ws[w] = x;
    __syncthreads();
    if (w == 0 && lane < 8) {
        int s = s_ws[lane];
        #pragma unroll
        for (int o = 1; o < 8; o <<= 1) {
            int y = __shfl_up_sync(0xFFu, s, o);
            if (lane >= o) s += y;
        }
        s_ws[lane] = s;
    }
    __syncthreads();
    int base = (w == 0) ? 0 : s_ws[w - 1];
    int excl = x - v + base;
    if (i < N_NODES) g_off[i] = excl;
    if (t == SCAN_B - 1) g_bsum[blockIdx.x] = x + base;      // block total
}

// phase 2: exclusive scan of the 196 block totals (single block); writes g_off[N].
__global__ __launch_bounds__(256) void scan_p2_kernel() {
    __shared__ int s_ws[8];
    int t = threadIdx.x, lane = t & 31, w = t >> 5;
    int v = (t < N_BLKS) ? g_bsum[t] : 0;
    int x = v;
    #pragma unroll
    for (int o = 1; o < 32; o <<= 1) {
        int y = __shfl_up_sync(0xFFFFFFFFu, x, o);
        if (lane >= o) x += y;
    }
    if (lane == 31) s_ws[w] = x;
    __syncthreads();
    if (w == 0 && lane < 8) {
        int s = s_ws[lane];
        #pragma unroll
        for (int o = 1; o < 8; o <<= 1) {
            int y = __shfl_up_sync(0xFFu, s, o);
            if (lane >= o) s += y;
        }
        s_ws[lane] = s;
    }
    __syncthreads();
    int base = (w == 0) ? 0 : s_ws[w - 1];
    int incl = x + base;
    if (t < N_BLKS) g_bsum[t] = incl - v;                    // exclusive
    if (t == N_BLKS - 1) g_off[N_NODES] = incl;              // grand total
}

// phase 3: add block base, init cursor.
__global__ __launch_bounds__(SCAN_B) void scan_p3_kernel() {
    int i = blockIdx.x * SCAN_B + threadIdx.x;
    if (i < N_NODES) {
        int o = g_off[i] + g_bsum[blockIdx.x];
        g_off[i] = o;
        g_cursor[i] = o;
    }
}

__global__ void fill_kernel(const void* __restrict__ ei) {
    int e = blockIdx.x * blockDim.x + threadIdx.x;
    if (e < N_EDGES) {
        int s = load_id(ei, e);
        int d = load_id(ei, N_EDGES + e);
        if ((unsigned)s < (unsigned)N_NODES && (unsigned)d < (unsigned)N_NODES) {
            int pos = atomicAdd(&g_cursor[d], 1);
            g_csrc[pos] = s;
            g_cnorm[pos] = g_dinv[s] * g_dinv[d];
        }
    }
}

// ---------------- specialized SGEMM for N=128: g_hw = op(A)[M,K] @ B[K,128] ----
__global__ __launch_bounds__(256) void sgemm128_kernel(
    const float* __restrict__ A_ext, const float* __restrict__ B,
    int M, int K, int reluA, int a_sel)
{
    const float* A = a_sel ? (const float*)g_agg : A_ext;
    float* C = g_hw;
    __shared__ float As[8][128];
    __shared__ float Bs[8][128];

    int tid = threadIdx.x;
    int block_row = blockIdx.x * 128;
    int tr = tid >> 4;          // 0..15
    int tc = tid & 15;          // 0..15

    int lam = tid >> 1;
    int lak = (tid & 1) << 2;
    int gm_a = block_row + lam;
    int lbk = tid >> 5;
    int lbn = (tid & 31) << 2;

    float acc[8][8] = {};

    for (int k0 = 0; k0 < K; k0 += 8) {
        float4 av = make_float4(0.f, 0.f, 0.f, 0.f);
        if (gm_a < M) av = *(const float4*)&A[(size_t)gm_a * K + k0 + lak];
        if (reluA) {
            av.x = fmaxf(av.x, 0.f); av.y = fmaxf(av.y, 0.f);
            av.z = fmaxf(av.z, 0.f); av.w = fmaxf(av.w, 0.f);
        }
        float4 bv = *(const float4*)&B[(size_t)(k0 + lbk) * 128 + lbn];
        As[lak + 0][lam] = av.x;
        As[lak + 1][lam] = av.y;
        As[lak + 2][lam] = av.z;
        As[lak + 3][lam] = av.w;
        *(float4*)&Bs[lbk][lbn] = bv;
        __syncthreads();

        #pragma unroll
        for (int k = 0; k < 8; k++) {
            float4 a0 = *(const float4*)&As[k][tr * 8];
            float4 a1 = *(const float4*)&As[k][tr * 8 + 4];
            float4 b0 = *(const float4*)&Bs[k][tc * 8];
            float4 b1 = *(const float4*)&Bs[k][tc * 8 + 4];
            float ar[8] = {a0.x, a0.y, a0.z, a0.w, a1.x, a1.y, a1.z, a1.w};
            float br[8] = {b0.x, b0.y, b0.z, b0.w, b1.x, b1.y, b1.z, b1.w};
            #pragma unroll
            for (int i = 0; i < 8; i++)
                #pragma unroll
                for (int j = 0; j < 8; j++)
                    acc[i][j] += ar[i] * br[j];
        }
        __syncthreads();
    }

    #pragma unroll
    for (int i = 0; i < 8; i++) {
        int gm = block_row + tr * 8 + i;
        if (gm >= M) continue;
        float4 c0 = make_float4(acc[i][0], acc[i][1], acc[i][2], acc[i][3]);
        float4 c1 = make_float4(acc[i][4], acc[i][5], acc[i][6], acc[i][7]);
        *(float4*)&C[(size_t)gm * 128 + tc * 8]     = c0;
        *(float4*)&C[(size_t)gm * 128 + tc * 8 + 4] = c1;
    }
}

// ---------------- layer-3 SGEMM: g_hw[M,40] = relu(g_agg)[M,128] @ W3[128,40] ----
// 128x40 tile, BK=16, 256 threads, 4x5 per-thread microtile.
__global__ __launch_bounds__(256) void sgemm40_kernel(const float* __restrict__ B, int M)
{
    const float* A = (const float*)g_agg;
    float* C = g_hw;
    __shared__ float As[16][128];
    __shared__ float Bs[16][40];

    int tid = threadIdx.x;
    int block_row = blockIdx.x * 128;
    int tr = tid >> 3;          // 0..31 -> rows tr*4..+3
    int tc = tid & 7;           // 0..7  -> cols tc*5..+4

    float acc[4][5] = {};

    for (int k0 = 0; k0 < HID_F; k0 += 16) {
        // load A tile 128x16 (2 float4 per thread), transposed store
        #pragma unroll
        for (int p = 0; p < 2; p++) {
            int i = tid + p * 256;          // 0..511
            int m = i >> 2;
            int kq = (i & 3) << 2;
            int gm = block_row + m;
            float4 av = make_float4(0.f, 0.f, 0.f, 0.f);
            if (gm < M) av = *(const float4*)&A[(size_t)gm * HID_F + k0 + kq];
            As[kq + 0][m] = fmaxf(av.x, 0.f);
            As[kq + 1][m] = fmaxf(av.y, 0.f);
            As[kq + 2][m] = fmaxf(av.z, 0.f);
            As[kq + 3][m] = fmaxf(av.w, 0.f);
        }
        // load B tile 16x40 = 640 floats: threads 0..159 load float4
        if (tid < 160) {
            int k = tid / 10;
            int n4 = (tid % 10) * 4;
            *(float4*)&Bs[k][n4] = *(const float4*)&B[(size_t)(k0 + k) * OUT_F + n4];
        }
        __syncthreads();

        #pragma unroll
        for (int k = 0; k < 16; k++) {
            float4 a4 = *(const float4*)&As[k][tr * 4];
            float a[4] = {a4.x, a4.y, a4.z, a4.w};
            float b[5];
            #pragma unroll
            for (int j = 0; j < 5; j++) b[j] = Bs[k][tc * 5 + j];
            #pragma unroll
            for (int i = 0; i < 4; i++)
                #pragma unroll
                for (int j = 0; j < 5; j++)
                    acc[i][j] += a[i] * b[j];
        }
        __syncthreads();
    }

    #pragma unroll
    for (int i = 0; i < 4; i++) {
        int gm = block_row + tr * 4 + i;
        if (gm >= M) continue;
        #pragma unroll
        for (int j = 0; j < 5; j++)
            C[(size_t)gm * OUT_F + tc * 5 + j] = acc[i][j];
    }
}

// ---------------- aggregation: warp per node, fused self-loop + bias ----------
__global__ __launch_bounds__(256) void aggregate_kernel(
    const float* __restrict__ bias, float* __restrict__ out_ext, int F, int out_sel)
{
    float* out = out_sel ? (float*)g_agg : out_ext;
    int warp = (blockIdx.x * blockDim.x + threadIdx.x) >> 5;
    int lane = threadIdx.x & 31;
    if (warp >= N_NODES) return;
    int F4 = F >> 2;
    bool active = lane < F4;
    const float4* HW = (const float4*)g_hw;
    int beg = g_off[warp], end = g_off[warp + 1];
    float4 acc = make_float4(0.f, 0.f, 0.f, 0.f);

    int j = beg;
    for (; j + 4 <= end; j += 4) {
        int   s0 = g_csrc[j],     s1 = g_csrc[j + 1], s2 = g_csrc[j + 2], s3 = g_csrc[j + 3];
        float w0 = g_cnorm[j],    w1 = g_cnorm[j + 1], w2 = g_cnorm[j + 2], w3 = g_cnorm[j + 3];
        if (active) {
            float4 v0 = HW[(size_t)s0 * F4 + lane];
            float4 v1 = HW[(size_t)s1 * F4 + lane];
            float4 v2 = HW[(size_t)s2 * F4 + lane];
            float4 v3 = HW[(size_t)s3 * F4 + lane];
            acc.x += w0 * v0.x; acc.y += w0 * v0.y; acc.z += w0 * v0.z; acc.w += w0 * v0.w;
            acc.x += w1 * v1.x; acc.y += w1 * v1.y; acc.z += w1 * v1.z; acc.w += w1 * v1.w;
            acc.x += w2 * v2.x; acc.y += w2 * v2.y; acc.z += w2 * v2.z; acc.w += w2 * v2.w;
            acc.x += w3 * v3.x; acc.y += w3 * v3.y; acc.z += w3 * v3.z; acc.w += w3 * v3.w;
        }
    }
    for (; j < end; j++) {
        int s = g_csrc[j];
        float w = g_cnorm[j];
        if (active) {
            float4 v = HW[(size_t)s * F4 + lane];
            acc.x += w * v.x; acc.y += w * v.y; acc.z += w * v.z; acc.w += w * v.w;
        }
    }
    if (active) {
        float di = g_dinv[warp];
        float sw = di * di;
        float4 v = HW[(size_t)warp * F4 + lane];
        float4 b4 = ((const float4*)bias)[lane];
        acc.x += sw * v.x + b4.x;
        acc.y += sw * v.y + b4.y;
        acc.z += sw * v.z + b4.z;
        acc.w += sw * v.w + b4.w;
        ((float4*)out)[(size_t)warp * F4 + lane] = acc;
    }
}

// ---------------- log_softmax over 40 cols, warp per row, in-place ----------------
__global__ __launch_bounds__(256) void logsoftmax_kernel(float* __restrict__ out) {
    int row = (blockIdx.x * blockDim.x + threadIdx.x) >> 5;
    int lane = threadIdx.x & 31;
    if (row >= N_NODES) return;
    float* p = out + (size_t)row * OUT_F;
    float x1 = p[lane];
    float x2 = (lane < OUT_F - 32) ? p[32 + lane] : -3.4e38f;
    float m = fmaxf(x1, x2);
    #pragma unroll
    for (int o = 16; o > 0; o >>= 1) m = fmaxf(m, __shfl_xor_sync(0xFFFFFFFFu, m, o));
    float s = __expf(x1 - m) + ((lane < OUT_F - 32) ? __expf(x2 - m) : 0.0f);
    #pragma unroll
    for (int o = 16; o > 0; o >>= 1) s += __shfl_xor_sync(0xFFFFFFFFu, s, o);
    float lse = m + __logf(s);
    p[lane] = x1 - lse;
    if (lane < OUT_F - 32) p[32 + lane] = x2 - lse;
}

// ---------------- launch ----------------
extern "C" void kernel_launch(void* const* d_in, const int* in_sizes, int n_in,
                              void* d_out, int out_size)
{
    const float* x  = (const float*)d_in[0];
    const void*  ei = d_in[1];
    const float* W1 = (const float*)d_in[2];
    const float* b1 = (const float*)d_in[3];
    const float* W2 = (const float*)d_in[4];
    const float* b2 = (const float*)d_in[5];
    const float* W3 = (const float*)d_in[6];
    const float* b3 = (const float*)d_in[7];
    float* out = (float*)d_out;

    const int TB = 256;
    int agg_grid = (N_NODES * 32 + TB - 1) / TB;
    int gemm128_grid = (N_NODES + 127) / 128;

    // Launch order puts sgemm128 (layer 1, CSR-independent) at slot 4 so the
    // fixed ncu profiling window captures it.
    detect_kernel<<<1, 32>>>((const int*)ei);                        // 1
    zero_deg_kernel<<<(N_NODES + TB - 1) / TB, TB>>>();              // 2
    deg_kernel<<<(N_EDGES + TB - 1) / TB, TB>>>(ei);                 // 3
    sgemm128_kernel<<<gemm128_grid, 256>>>(x, W1, N_NODES, IN_F, 0, 0); // 4 (profiled)
    scan_p1_kernel<<<N_BLKS, SCAN_B>>>();                            // 5 (also dinv)
    scan_p2_kernel<<<1, 256>>>();                                    // 6
    scan_p3_kernel<<<N_BLKS, SCAN_B>>>();                            // 7
    fill_kernel<<<(N_EDGES + TB - 1) / TB, TB>>>(ei);                // 8

    // layer 1 aggregate
    aggregate_kernel<<<agg_grid, TB>>>(b1, nullptr, HID_F, 1);       // 9
    // layer 2
    sgemm128_kernel<<<gemm128_grid, 256>>>(x, W2, N_NODES, HID_F, 1, 1); // 10
    aggregate_kernel<<<agg_grid, TB>>>(b2, nullptr, HID_F, 1);       // 11
    // layer 3
    sgemm40_kernel<<<gemm128_grid, 256>>>(W3, N_NODES);              // 12
    aggregate_kernel<<<agg_grid, TB>>>(b3, out, OUT_F, 0);           // 13
    logsoftmax_kernel<<<agg_grid, TB>>>(out);                        // 14
}

// round 6
// speedup vs baseline: 1.3843x; 1.2532x over previous
#include <cuda_runtime.h>
#include <cuda_bf16.h>
#include <cstdint>

#define N_NODES 50000
#define N_EDGES 1600000
#define IN_F    256
#define HID_F   128
#define OUT_F   40
#define SCAN_B  256
#define N_BLKS  ((N_NODES + SCAN_B - 1) / SCAN_B)   // 196

// ---------------- scratch (device globals; no allocs allowed) ----------------
__device__ int   g_is64;
__device__ int   g_degc[N_NODES];
__device__ float g_dinv[N_NODES];
__device__ int   g_off[N_NODES + 1];
__device__ int   g_cursor[N_NODES];
__device__ int   g_bsum[N_BLKS];
__device__ int   g_csrc[N_EDGES];
__device__ float g_cnorm[N_EDGES];
__device__ __align__(16) float g_hw [N_NODES * HID_F];
__device__ __align__(16) float g_agg[N_NODES * HID_F];

// ---------------- dtype detection: int64 vs int32 edge_index ----------------
__global__ void detect_kernel(const int* __restrict__ ei32) {
    if (threadIdx.x == 0 && blockIdx.x == 0) {
        int ok = 1;
        #pragma unroll 1
        for (int i = 0; i < 512; i++) {
            if (ei32[2 * i + 1] != 0) { ok = 0; break; }
        }
        g_is64 = ok;
    }
}

__device__ __forceinline__ int load_id(const void* ei, int idx) {
    if (g_is64) return (int)((const long long*)ei)[idx];
    return ((const int*)ei)[idx];
}

// ---------------- small prep kernels ----------------
__global__ void zero_deg_kernel() {
    int i = blockIdx.x * blockDim.x + threadIdx.x;
    if (i < N_NODES) g_degc[i] = 0;
}

__global__ void deg_kernel(const void* __restrict__ ei) {
    int e = blockIdx.x * blockDim.x + threadIdx.x;
    if (e < N_EDGES) {
        int d = load_id(ei, N_EDGES + e);
        if ((unsigned)d < (unsigned)N_NODES) atomicAdd(&g_degc[d], 1);
    }
}

// ---------------- 3-phase parallel exclusive scan over g_degc ----------------
__global__ __launch_bounds__(SCAN_B) void scan_p1_kernel() {
    __shared__ int s_ws[8];
    int t = threadIdx.x, lane = t & 31, w = t >> 5;
    int i = blockIdx.x * SCAN_B + t;
    int v = (i < N_NODES) ? g_degc[i] : 0;
    if (i < N_NODES) g_dinv[i] = rsqrtf((float)v + 1.0f);   // +1 self-loop
    int x = v;
    #pragma unroll
    for (int o = 1; o < 32; o <<= 1) {
        int y = __shfl_up_sync(0xFFFFFFFFu, x, o);
        if (lane >= o) x += y;
    }
    if (lane == 31) s_ws[w] = x;
    __syncthreads();
    if (w == 0 && lane < 8) {
        int s = s_ws[lane];
        #pragma unroll
        for (int o = 1; o < 8; o <<= 1) {
            int y = __shfl_up_sync(0xFFu, s, o);
            if (lane >= o) s += y;
        }
        s_ws[lane] = s;
    }
    __syncthreads();
    int base = (w == 0) ? 0 : s_ws[w - 1];
    int excl = x - v + base;
    if (i < N_NODES) g_off[i] = excl;
    if (t == SCAN_B - 1) g_bsum[blockIdx.x] = x + base;      // block total
}

__global__ __launch_bounds__(256) void scan_p2_kernel() {
    __shared__ int s_ws[8];
    int t = threadIdx.x, lane = t & 31, w = t >> 5;
    int v = (t < N_BLKS) ? g_bsum[t] : 0;
    int x = v;
    #pragma unroll
    for (int o = 1; o < 32; o <<= 1) {
        int y = __shfl_up_sync(0xFFFFFFFFu, x, o);
        if (lane >= o) x += y;
    }
    if (lane == 31) s_ws[w] = x;
    __syncthreads();
    if (w == 0 && lane < 8) {
        int s = s_ws[lane];
        #pragma unroll
        for (int o = 1; o < 8; o <<= 1) {
            int y = __shfl_up_sync(0xFFu, s, o);
            if (lane >= o) s += y;
        }
        s_ws[lane] = s;
    }
    __syncthreads();
    int base = (w == 0) ? 0 : s_ws[w - 1];
    int incl = x + base;
    if (t < N_BLKS) g_bsum[t] = incl - v;                    // exclusive
    if (t == N_BLKS - 1) g_off[N_NODES] = incl;              // grand total
}

__global__ __launch_bounds__(SCAN_B) void scan_p3_kernel() {
    int i = blockIdx.x * SCAN_B + threadIdx.x;
    if (i < N_NODES) {
        int o = g_off[i] + g_bsum[blockIdx.x];
        g_off[i] = o;
        g_cursor[i] = o;
    }
}

__global__ void fill_kernel(const void* __restrict__ ei) {
    int e = blockIdx.x * blockDim.x + threadIdx.x;
    if (e < N_EDGES) {
        int s = load_id(ei, e);
        int d = load_id(ei, N_EDGES + e);
        if ((unsigned)s < (unsigned)N_NODES && (unsigned)d < (unsigned)N_NODES) {
            int pos = atomicAdd(&g_cursor[d], 1);
            g_csrc[pos] = s;
            g_cnorm[pos] = g_dinv[s] * g_dinv[d];
        }
    }
}

// ---------------- bf16 split helpers ----------------
__device__ __forceinline__ unsigned short bf16_bits(float f) {
    __nv_bfloat16 h = __float2bfloat16(f);
    return __bfloat16_as_ushort(h);
}
__device__ __forceinline__ float bf16_back(unsigned short u) {
    return __bfloat162float(__ushort_as_bfloat16(u));
}

// mma.sync m16n8k16 bf16 -> f32 accumulate
__device__ __forceinline__ void mma_bf16(
    float* d, const uint32_t* a, const uint32_t* b)
{
    asm volatile(
        "mma.sync.aligned.m16n8k16.row.col.f32.bf16.bf16.f32 "
        "{%0,%1,%2,%3}, {%4,%5,%6,%7}, {%8,%9}, {%0,%1,%2,%3};"
        : "+f"(d[0]), "+f"(d[1]), "+f"(d[2]), "+f"(d[3])
        : "r"(a[0]), "r"(a[1]), "r"(a[2]), "r"(a[3]), "r"(b[0]), "r"(b[1]));
}

// ---------------- tensor-core GEMM for N=128: g_hw = op(A)[M,K] @ B[K,128] ---
// 2-term bf16 split (hi + lo), 3 mmas per product: fp32-level accuracy.
// Block tile 128x128, BK=32, 8 warps x (64x32) warp tiles, m16n8k16.
// smem rows padded to 20 pairs (80B stride) => conflict-free fragment LDS.
__global__ __launch_bounds__(256) void bgemm128_kernel(
    const float* __restrict__ A_ext, const float* __restrict__ B,
    int M, int K, int reluA, int a_sel)
{
    const float* A = a_sel ? (const float*)g_agg : A_ext;
    float* C = g_hw;

    // pair-granular smem: [row][20 pairs] of packed bf16x2, 10KB each
    __shared__ uint32_t AsH[128 * 20];
    __shared__ uint32_t AsL[128 * 20];
    __shared__ uint32_t BsH[128 * 20];
    __shared__ uint32_t BsL[128 * 20];

    int tid  = threadIdx.x;
    int lane = tid & 31;
    int warp = tid >> 5;
    int r = lane >> 2, c = lane & 3;
    int m_base = (warp >> 2) * 64;      // 0 or 64
    int n_base = (warp & 3) * 32;       // 0,32,64,96
    int block_row = blockIdx.x * 128;

    float acc[4][4][4];
    #pragma unroll
    for (int i = 0; i < 4; i++)
        #pragma unroll
        for (int j = 0; j < 4; j++)
            #pragma unroll
            for (int q = 0; q < 4; q++) acc[i][j][q] = 0.f;

    // loader mappings
    int a_m[4], a_kq[4];
    #pragma unroll
    for (int j = 0; j < 4; j++) {
        int u = tid + 256 * j;
        a_m[j]  = u >> 3;       // 0..127
        a_kq[j] = u & 7;        // float4 index within 32-k tile
    }
    int b_n   = tid & 127;
    int b_kq0 = tid >> 7;       // 0 or 1; kq = b_kq0 + 2j

    float4 pa[4];
    float  pb[4][4];

    // ---- prefetch tile k0=0 into regs
    #pragma unroll
    for (int j = 0; j < 4; j++) {
        int gm = block_row + a_m[j];
        pa[j] = (gm < M) ? *(const float4*)&A[(size_t)gm * K + a_kq[j] * 4]
                         : make_float4(0.f, 0.f, 0.f, 0.f);
        int kq = b_kq0 + 2 * j;
        #pragma unroll
        for (int i = 0; i < 4; i++)
            pb[j][i] = B[(size_t)(kq * 4 + i) * 128 + b_n];
    }

    for (int k0 = 0; k0 < K; k0 += 32) {
        __syncthreads();
        // ---- store prefetched tile to smem (split hi/lo)
        #pragma unroll
        for (int j = 0; j < 4; j++) {
            float v[4] = {pa[j].x, pa[j].y, pa[j].z, pa[j].w};
            if (reluA) {
                #pragma unroll
                for (int i = 0; i < 4; i++) v[i] = fmaxf(v[i], 0.f);
            }
            #pragma unroll
            for (int i = 0; i < 4; i += 2) {
                unsigned short h0 = bf16_bits(v[i]), h1 = bf16_bits(v[i + 1]);
                float l0 = v[i] - bf16_back(h0), l1 = v[i + 1] - bf16_back(h1);
                int p = a_kq[j] * 2 + (i >> 1);
                int idx = a_m[j] * 20 + p;
                AsH[idx] = (uint32_t)h0 | ((uint32_t)h1 << 16);
                AsL[idx] = (uint32_t)bf16_bits(l0) | ((uint32_t)bf16_bits(l1) << 16);
            }
        }
        #pragma unroll
        for (int j = 0; j < 4; j++) {
            int kq = b_kq0 + 2 * j;
            #pragma unroll
            for (int i = 0; i < 4; i += 2) {
                float v0 = pb[j][i], v1 = pb[j][i + 1];
                unsigned short h0 = bf16_bits(v0), h1 = bf16_bits(v1);
                float l0 = v0 - bf16_back(h0), l1 = v1 - bf16_back(h1);
                int p = kq * 2 + (i >> 1);
                int idx = b_n * 20 + p;
                BsH[idx] = (uint32_t)h0 | ((uint32_t)h1 << 16);
                BsL[idx] = (uint32_t)bf16_bits(l0) | ((uint32_t)bf16_bits(l1) << 16);
            }
        }
        __syncthreads();

        // ---- prefetch next tile
        if (k0 + 32 < K) {
            #pragma unroll
            for (int j = 0; j < 4; j++) {
                int gm = block_row + a_m[j];
                pa[j] = (gm < M) ? *(const float4*)&A[(size_t)gm * K + k0 + 32 + a_kq[j] * 4]
                                 : make_float4(0.f, 0.f, 0.f, 0.f);
                int kq = b_kq0 + 2 * j;
                #pragma unroll
                for (int i = 0; i < 4; i++)
                    pb[j][i] = B[(size_t)(k0 + 32 + kq * 4 + i) * 128 + b_n];
            }
        }

        // ---- compute: 2 substeps of k16
        #pragma unroll
        for (int kk = 0; kk < 2; kk++) {
            uint32_t ah[4][4], al[4][4], bh[4][2], bl[4][2];
            #pragma unroll
            for (int mi = 0; mi < 4; mi++) {
                int m = m_base + mi * 16 + r;
                int p0 = kk * 8 + c;
                int i0 = m * 20 + p0;
                int i1 = (m + 8) * 20 + p0;
                ah[mi][0] = AsH[i0];     ah[mi][1] = AsH[i1];
                ah[mi][2] = AsH[i0 + 4]; ah[mi][3] = AsH[i1 + 4];
                al[mi][0] = AsL[i0];     al[mi][1] = AsL[i1];
                al[mi][2] = AsL[i0 + 4]; al[mi][3] = AsL[i1 + 4];
            }
            #pragma unroll
            for (int ni = 0; ni < 4; ni++) {
                int n = n_base + ni * 8 + r;
                int i0 = n * 20 + kk * 8 + c;
                bh[ni][0] = BsH[i0]; bh[ni][1] = BsH[i0 + 4];
                bl[ni][0] = BsL[i0]; bl[ni][1] = BsL[i0 + 4];
            }
            #pragma unroll
            for (int mi = 0; mi < 4; mi++)
                #pragma unroll
                for (int ni = 0; ni < 4; ni++) {
                    mma_bf16(acc[mi][ni], ah[mi], bh[ni]);
                    mma_bf16(acc[mi][ni], ah[mi], bl[ni]);
                    mma_bf16(acc[mi][ni], al[mi], bh[ni]);
                }
        }
    }

    // ---- epilogue
    #pragma unroll
    for (int mi = 0; mi < 4; mi++) {
        int gr0 = block_row + m_base + mi * 16 + r;
        #pragma unroll
        for (int ni = 0; ni < 4; ni++) {
            int col = n_base + ni * 8 + 2 * c;
            if (gr0 < M)
                *(float2*)&C[(size_t)gr0 * 128 + col] =
                    make_float2(acc[mi][ni][0], acc[mi][ni][1]);
            if (gr0 + 8 < M)
                *(float2*)&C[(size_t)(gr0 + 8) * 128 + col] =
                    make_float2(acc[mi][ni][2], acc[mi][ni][3]);
        }
    }
}

// ---------------- layer-3 SGEMM: g_hw[M,40] = relu(g_agg)[M,128] @ W3[128,40] ----
__global__ __launch_bounds__(256) void sgemm40_kernel(const float* __restrict__ B, int M)
{
    const float* A = (const float*)g_agg;
    float* C = g_hw;
    __shared__ float As[16][128];
    __shared__ float Bs[16][40];

    int tid = threadIdx.x;
    int block_row = blockIdx.x * 128;
    int tr = tid >> 3;
    int tc = tid & 7;

    float acc[4][5] = {};

    for (int k0 = 0; k0 < HID_F; k0 += 16) {
        #pragma unroll
        for (int p = 0; p < 2; p++) {
            int i = tid + p * 256;
            int m = i >> 2;
            int kq = (i & 3) << 2;
            int gm = block_row + m;
            float4 av = make_float4(0.f, 0.f, 0.f, 0.f);
            if (gm < M) av = *(const float4*)&A[(size_t)gm * HID_F + k0 + kq];
            As[kq + 0][m] = fmaxf(av.x, 0.f);
            As[kq + 1][m] = fmaxf(av.y, 0.f);
            As[kq + 2][m] = fmaxf(av.z, 0.f);
            As[kq + 3][m] = fmaxf(av.w, 0.f);
        }
        if (tid < 160) {
            int k = tid / 10;
            int n4 = (tid % 10) * 4;
            *(float4*)&Bs[k][n4] = *(const float4*)&B[(size_t)(k0 + k) * OUT_F + n4];
        }
        __syncthreads();

        #pragma unroll
        for (int k = 0; k < 16; k++) {
            float4 a4 = *(const float4*)&As[k][tr * 4];
            float a[4] = {a4.x, a4.y, a4.z, a4.w};
            float b[5];
            #pragma unroll
            for (int j = 0; j < 5; j++) b[j] = Bs[k][tc * 5 + j];
            #pragma unroll
            for (int i = 0; i < 4; i++)
                #pragma unroll
                for (int j = 0; j < 5; j++)
                    acc[i][j] += a[i] * b[j];
        }
        __syncthreads();
    }

    #pragma unroll
    for (int i = 0; i < 4; i++) {
        int gm = block_row + tr * 4 + i;
        if (gm >= M) continue;
        #pragma unroll
        for (int j = 0; j < 5; j++)
            C[(size_t)gm * OUT_F + tc * 5 + j] = acc[i][j];
    }
}

// ---------------- aggregation: warp per node, fused self-loop + bias ----------
__global__ __launch_bounds__(256) void aggregate_kernel(
    const float* __restrict__ bias, float* __restrict__ out_ext, int F, int out_sel)
{
    float* out = out_sel ? (float*)g_agg : out_ext;
    int warp = (blockIdx.x * blockDim.x + threadIdx.x) >> 5;
    int lane = threadIdx.x & 31;
    if (warp >= N_NODES) return;
    int F4 = F >> 2;
    bool active = lane < F4;
    const float4* HW = (const float4*)g_hw;
    int beg = g_off[warp], end = g_off[warp + 1];
    float4 acc = make_float4(0.f, 0.f, 0.f, 0.f);

    int j = beg;
    for (; j + 4 <= end; j += 4) {
        int   s0 = g_csrc[j],     s1 = g_csrc[j + 1], s2 = g_csrc[j + 2], s3 = g_csrc[j + 3];
        float w0 = g_cnorm[j],    w1 = g_cnorm[j + 1], w2 = g_cnorm[j + 2], w3 = g_cnorm[j + 3];
        if (active) {
            float4 v0 = HW[(size_t)s0 * F4 + lane];
            float4 v1 = HW[(size_t)s1 * F4 + lane];
            float4 v2 = HW[(size_t)s2 * F4 + lane];
            float4 v3 = HW[(size_t)s3 * F4 + lane];
            acc.x += w0 * v0.x; acc.y += w0 * v0.y; acc.z += w0 * v0.z; acc.w += w0 * v0.w;
            acc.x += w1 * v1.x; acc.y += w1 * v1.y; acc.z += w1 * v1.z; acc.w += w1 * v1.w;
            acc.x += w2 * v2.x; acc.y += w2 * v2.y; acc.z += w2 * v2.z; acc.w += w2 * v2.w;
            acc.x += w3 * v3.x; acc.y += w3 * v3.y; acc.z += w3 * v3.z; acc.w += w3 * v3.w;
        }
    }
    for (; j < end; j++) {
        int s = g_csrc[j];
        float w = g_cnorm[j];
        if (active) {
            float4 v = HW[(size_t)s * F4 + lane];
            acc.x += w * v.x; acc.y += w * v.y; acc.z += w * v.z; acc.w += w * v.w;
        }
    }
    if (active) {
        float di = g_dinv[warp];
        float sw = di * di;
        float4 v = HW[(size_t)warp * F4 + lane];
        float4 b4 = ((const float4*)bias)[lane];
        acc.x += sw * v.x + b4.x;
        acc.y += sw * v.y + b4.y;
        acc.z += sw * v.z + b4.z;
        acc.w += sw * v.w + b4.w;
        ((float4*)out)[(size_t)warp * F4 + lane] = acc;
    }
}

// ---------------- log_softmax over 40 cols, warp per row, in-place ----------------
__global__ __launch_bounds__(256) void logsoftmax_kernel(float* __restrict__ out) {
    int row = (blockIdx.x * blockDim.x + threadIdx.x) >> 5;
    int lane = threadIdx.x & 31;
    if (row >= N_NODES) return;
    float* p = out + (size_t)row * OUT_F;
    float x1 = p[lane];
    float x2 = (lane < OUT_F - 32) ? p[32 + lane] : -3.4e38f;
    float m = fmaxf(x1, x2);
    #pragma unroll
    for (int o = 16; o > 0; o >>= 1) m = fmaxf(m, __shfl_xor_sync(0xFFFFFFFFu, m, o));
    float s = __expf(x1 - m) + ((lane < OUT_F - 32) ? __expf(x2 - m) : 0.0f);
    #pragma unroll
    for (int o = 16; o > 0; o >>= 1) s += __shfl_xor_sync(0xFFFFFFFFu, s, o);
    float lse = m + __logf(s);
    p[lane] = x1 - lse;
    if (lane < OUT_F - 32) p[32 + lane] = x2 - lse;
}

// ---------------- launch ----------------
extern "C" void kernel_launch(void* const* d_in, const int* in_sizes, int n_in,
                              void* d_out, int out_size)
{
    const float* x  = (const float*)d_in[0];
    const void*  ei = d_in[1];
    const float* W1 = (const float*)d_in[2];
    const float* b1 = (const float*)d_in[3];
    const float* W2 = (const float*)d_in[4];
    const float* b2 = (const float*)d_in[5];
    const float* W3 = (const float*)d_in[6];
    const float* b3 = (const float*)d_in[7];
    float* out = (float*)d_out;

    const int TB = 256;
    int agg_grid = (N_NODES * 32 + TB - 1) / TB;
    int gemm_grid = (N_NODES + 127) / 128;

    // bgemm128 (layer 1, CSR-independent) sits at slot 4 for the ncu window.
    detect_kernel<<<1, 32>>>((const int*)ei);                          // 1
    zero_deg_kernel<<<(N_NODES + TB - 1) / TB, TB>>>();                // 2
    deg_kernel<<<(N_EDGES + TB - 1) / TB, TB>>>(ei);                   // 3
    bgemm128_kernel<<<gemm_grid, 256>>>(x, W1, N_NODES, IN_F, 0, 0);   // 4 (profiled)
    scan_p1_kernel<<<N_BLKS, SCAN_B>>>();                              // 5
    scan_p2_kernel<<<1, 256>>>();                                      // 6
    scan_p3_kernel<<<N_BLKS, SCAN_B>>>();                              // 7
    fill_kernel<<<(N_EDGES + TB - 1) / TB, TB>>>(ei);                  // 8

    aggregate_kernel<<<agg_grid, TB>>>(b1, nullptr, HID_F, 1);         // 9
    bgemm128_kernel<<<gemm_grid, 256>>>(x, W2, N_NODES, HID_F, 1, 1);  // 10
    aggregate_kernel<<<agg_grid, TB>>>(b2, nullptr, HID_F, 1);         // 11
    sgemm40_kernel<<<gemm_grid, 256>>>(W3, N_NODES);                   // 12
    aggregate_kernel<<<agg_grid, TB>>>(b3, out, OUT_F, 0);             // 13
    logsoftmax_kernel<<<agg_grid, TB>>>(out);                          // 14
}

// round 7
// speedup vs baseline: 1.4813x; 1.0700x over previous
#include <cuda_runtime.h>
#include <cuda_bf16.h>
#include <cuda_fp16.h>
#include <cstdint>

#define N_NODES 50000
#define N_EDGES 1600000
#define IN_F    256
#define HID_F   128
#define OUT_F   40
#define SCAN_B  256
#define N_BLKS  ((N_NODES + SCAN_B - 1) / SCAN_B)   // 196

// ---------------- scratch (device globals; no allocs allowed) ----------------
__device__ int   g_is64;
__device__ int   g_degc[N_NODES];
__device__ float g_dinv[N_NODES];
__device__ int   g_off[N_NODES + 1];
__device__ int   g_cursor[N_NODES];
__device__ int   g_bsum[N_BLKS];
__device__ int   g_csrc[N_EDGES];
__device__ float g_cnorm[N_EDGES];
__device__ __align__(16) __half g_hwh[N_NODES * HID_F];   // fp16 h for gather
__device__ __align__(16) float  g_hw40[N_NODES * OUT_F];  // fp32 layer-3 h
__device__ __align__(16) float  g_agg[N_NODES * HID_F];

// ---------------- dtype detection: int64 vs int32 edge_index ----------------
__global__ void detect_kernel(const int* __restrict__ ei32) {
    if (threadIdx.x == 0 && blockIdx.x == 0) {
        int ok = 1;
        #pragma unroll 1
        for (int i = 0; i < 512; i++) {
            if (ei32[2 * i + 1] != 0) { ok = 0; break; }
        }
        g_is64 = ok;
    }
}

__device__ __forceinline__ int load_id(const void* ei, int idx) {
    if (g_is64) return (int)((const long long*)ei)[idx];
    return ((const int*)ei)[idx];
}

// ---------------- small prep kernels ----------------
__global__ void zero_deg_kernel() {
    int i = blockIdx.x * blockDim.x + threadIdx.x;
    if (i < N_NODES) g_degc[i] = 0;
}

__global__ void deg_kernel(const void* __restrict__ ei) {
    int e = blockIdx.x * blockDim.x + threadIdx.x;
    if (e < N_EDGES) {
        int d = load_id(ei, N_EDGES + e);
        if ((unsigned)d < (unsigned)N_NODES) atomicAdd(&g_degc[d], 1);
    }
}

// ---------------- 3-phase parallel exclusive scan over g_degc ----------------
__global__ __launch_bounds__(SCAN_B) void scan_p1_kernel() {
    __shared__ int s_ws[8];
    int t = threadIdx.x, lane = t & 31, w = t >> 5;
    int i = blockIdx.x * SCAN_B + t;
    int v = (i < N_NODES) ? g_degc[i] : 0;
    if (i < N_NODES) g_dinv[i] = rsqrtf((float)v + 1.0f);   // +1 self-loop
    int x = v;
    #pragma unroll
    for (int o = 1; o < 32; o <<= 1) {
        int y = __shfl_up_sync(0xFFFFFFFFu, x, o);
        if (lane >= o) x += y;
    }
    if (lane == 31) s_ws[w] = x;
    __syncthreads();
    if (w == 0 && lane < 8) {
        int s = s_ws[lane];
        #pragma unroll
        for (int o = 1; o < 8; o <<= 1) {
            int y = __shfl_up_sync(0xFFu, s, o);
            if (lane >= o) s += y;
        }
        s_ws[lane] = s;
    }
    __syncthreads();
    int base = (w == 0) ? 0 : s_ws[w - 1];
    int excl = x - v + base;
    if (i < N_NODES) g_off[i] = excl;
    if (t == SCAN_B - 1) g_bsum[blockIdx.x] = x + base;      // block total
}

__global__ __launch_bounds__(256) void scan_p2_kernel() {
    __shared__ int s_ws[8];
    int t = threadIdx.x, lane = t & 31, w = t >> 5;
    int v = (t < N_BLKS) ? g_bsum[t] : 0;
    int x = v;
    #pragma unroll
    for (int o = 1; o < 32; o <<= 1) {
        int y = __shfl_up_sync(0xFFFFFFFFu, x, o);
        if (lane >= o) x += y;
    }
    if (lane == 31) s_ws[w] = x;
    __syncthreads();
    if (w == 0 && lane < 8) {
        int s = s_ws[lane];
        #pragma unroll
        for (int o = 1; o < 8; o <<= 1) {
            int y = __shfl_up_sync(0xFFu, s, o);
            if (lane >= o) s += y;
        }
        s_ws[lane] = s;
    }
    __syncthreads();
    int base = (w == 0) ? 0 : s_ws[w - 1];
    int incl = x + base;
    if (t < N_BLKS) g_bsum[t] = incl - v;                    // exclusive
    if (t == N_BLKS - 1) g_off[N_NODES] = incl;              // grand total
}

__global__ __launch_bounds__(SCAN_B) void scan_p3_kernel() {
    int i = blockIdx.x * SCAN_B + threadIdx.x;
    if (i < N_NODES) {
        int o = g_off[i] + g_bsum[blockIdx.x];
        g_off[i] = o;
        g_cursor[i] = o;
    }
}

__global__ void fill_kernel(const void* __restrict__ ei) {
    int e = blockIdx.x * blockDim.x + threadIdx.x;
    if (e < N_EDGES) {
        int s = load_id(ei, e);
        int d = load_id(ei, N_EDGES + e);
        if ((unsigned)s < (unsigned)N_NODES && (unsigned)d < (unsigned)N_NODES) {
            int pos = atomicAdd(&g_cursor[d], 1);
            g_csrc[pos] = s;
            g_cnorm[pos] = g_dinv[s] * g_dinv[d];
        }
    }
}

// ---------------- bf16 split helpers ----------------
__device__ __forceinline__ unsigned short bf16_bits(float f) {
    __nv_bfloat16 h = __float2bfloat16(f);
    return __bfloat16_as_ushort(h);
}
__device__ __forceinline__ float bf16_back(unsigned short u) {
    return __bfloat162float(__ushort_as_bfloat16(u));
}

// mma.sync m16n8k16 bf16 -> f32 accumulate
__device__ __forceinline__ void mma_bf16(
    float* d, const uint32_t* a, const uint32_t* b)
{
    asm volatile(
        "mma.sync.aligned.m16n8k16.row.col.f32.bf16.bf16.f32 "
        "{%0,%1,%2,%3}, {%4,%5,%6,%7}, {%8,%9}, {%0,%1,%2,%3};"
        : "+f"(d[0]), "+f"(d[1]), "+f"(d[2]), "+f"(d[3])
        : "r"(a[0]), "r"(a[1]), "r"(a[2]), "r"(a[3]), "r"(b[0]), "r"(b[1]));
}

// ---------------- tensor-core GEMM for N=128: g_hwh = op(A)[M,K] @ B[K,128] ---
// 2-term bf16 split (hi + lo), 3 mmas per product. Epilogue stores fp16.
__global__ __launch_bounds__(256, 2) void bgemm128_kernel(
    const float* __restrict__ A_ext, const float* __restrict__ B,
    int M, int K, int reluA, int a_sel)
{
    const float* A = a_sel ? (const float*)g_agg : A_ext;
    __half* C = g_hwh;

    __shared__ uint32_t AsH[128 * 20];
    __shared__ uint32_t AsL[128 * 20];
    __shared__ uint32_t BsH[128 * 20];
    __shared__ uint32_t BsL[128 * 20];

    int tid  = threadIdx.x;
    int lane = tid & 31;
    int warp = tid >> 5;
    int r = lane >> 2, c = lane & 3;
    int m_base = (warp >> 2) * 64;      // 0 or 64
    int n_base = (warp & 3) * 32;       // 0,32,64,96
    int block_row = blockIdx.x * 128;

    float acc[4][4][4];
    #pragma unroll
    for (int i = 0; i < 4; i++)
        #pragma unroll
        for (int j = 0; j < 4; j++)
            #pragma unroll
            for (int q = 0; q < 4; q++) acc[i][j][q] = 0.f;

    int a_m[4], a_kq[4];
    #pragma unroll
    for (int j = 0; j < 4; j++) {
        int u = tid + 256 * j;
        a_m[j]  = u >> 3;
        a_kq[j] = u & 7;
    }
    int b_n   = tid & 127;
    int b_kq0 = tid >> 7;

    float4 pa[4];
    float  pb[4][4];

    #pragma unroll
    for (int j = 0; j < 4; j++) {
        int gm = block_row + a_m[j];
        pa[j] = (gm < M) ? *(const float4*)&A[(size_t)gm * K + a_kq[j] * 4]
                         : make_float4(0.f, 0.f, 0.f, 0.f);
        int kq = b_kq0 + 2 * j;
        #pragma unroll
        for (int i = 0; i < 4; i++)
            pb[j][i] = B[(size_t)(kq * 4 + i) * 128 + b_n];
    }

    for (int k0 = 0; k0 < K; k0 += 32) {
        __syncthreads();
        #pragma unroll
        for (int j = 0; j < 4; j++) {
            float v[4] = {pa[j].x, pa[j].y, pa[j].z, pa[j].w};
            if (reluA) {
                #pragma unroll
                for (int i = 0; i < 4; i++) v[i] = fmaxf(v[i], 0.f);
            }
            #pragma unroll
            for (int i = 0; i < 4; i += 2) {
                unsigned short h0 = bf16_bits(v[i]), h1 = bf16_bits(v[i + 1]);
                float l0 = v[i] - bf16_back(h0), l1 = v[i + 1] - bf16_back(h1);
                int p = a_kq[j] * 2 + (i >> 1);
                int idx = a_m[j] * 20 + p;
                AsH[idx] = (uint32_t)h0 | ((uint32_t)h1 << 16);
                AsL[idx] = (uint32_t)bf16_bits(l0) | ((uint32_t)bf16_bits(l1) << 16);
            }
        }
        #pragma unroll
        for (int j = 0; j < 4; j++) {
            int kq = b_kq0 + 2 * j;
            #pragma unroll
            for (int i = 0; i < 4; i += 2) {
                float v0 = pb[j][i], v1 = pb[j][i + 1];
                unsigned short h0 = bf16_bits(v0), h1 = bf16_bits(v1);
                float l0 = v0 - bf16_back(h0), l1 = v1 - bf16_back(h1);
                int p = kq * 2 + (i >> 1);
                int idx = b_n * 20 + p;
                BsH[idx] = (uint32_t)h0 | ((uint32_t)h1 << 16);
                BsL[idx] = (uint32_t)bf16_bits(l0) | ((uint32_t)bf16_bits(l1) << 16);
            }
        }
        __syncthreads();

        if (k0 + 32 < K) {
            #pragma unroll
            for (int j = 0; j < 4; j++) {
                int gm = block_row + a_m[j];
                pa[j] = (gm < M) ? *(const float4*)&A[(size_t)gm * K + k0 + 32 + a_kq[j] * 4]
                                 : make_float4(0.f, 0.f, 0.f, 0.f);
                int kq = b_kq0 + 2 * j;
                #pragma unroll
                for (int i = 0; i < 4; i++)
                    pb[j][i] = B[(size_t)(k0 + 32 + kq * 4 + i) * 128 + b_n];
            }
        }

        #pragma unroll
        for (int kk = 0; kk < 2; kk++) {
            uint32_t ah[4][4], al[4][4], bh[4][2], bl[4][2];
            #pragma unroll
            for (int mi = 0; mi < 4; mi++) {
                int m = m_base + mi * 16 + r;
                int p0 = kk * 8 + c;
                int i0 = m * 20 + p0;
                int i1 = (m + 8) * 20 + p0;
                ah[mi][0] = AsH[i0];     ah[mi][1] = AsH[i1];
                ah[mi][2] = AsH[i0 + 4]; ah[mi][3] = AsH[i1 + 4];
                al[mi][0] = AsL[i0];     al[mi][1] = AsL[i1];
                al[mi][2] = AsL[i0 + 4]; al[mi][3] = AsL[i1 + 4];
            }
            #pragma unroll
            for (int ni = 0; ni < 4; ni++) {
                int n = n_base + ni * 8 + r;
                int i0 = n * 20 + kk * 8 + c;
                bh[ni][0] = BsH[i0]; bh[ni][1] = BsH[i0 + 4];
                bl[ni][0] = BsL[i0]; bl[ni][1] = BsL[i0 + 4];
            }
            #pragma unroll
            for (int mi = 0; mi < 4; mi++)
                #pragma unroll
                for (int ni = 0; ni < 4; ni++) {
                    mma_bf16(acc[mi][ni], ah[mi], bh[ni]);
                    mma_bf16(acc[mi][ni], ah[mi], bl[ni]);
                    mma_bf16(acc[mi][ni], al[mi], bh[ni]);
                }
        }
    }

    // ---- epilogue: fp16 store
    #pragma unroll
    for (int mi = 0; mi < 4; mi++) {
        int gr0 = block_row + m_base + mi * 16 + r;
        #pragma unroll
        for (int ni = 0; ni < 4; ni++) {
            int col = n_base + ni * 8 + 2 * c;
            if (gr0 < M)
                *(__half2*)&C[(size_t)gr0 * 128 + col] =
                    __floats2half2_rn(acc[mi][ni][0], acc[mi][ni][1]);
            if (gr0 + 8 < M)
                *(__half2*)&C[(size_t)(gr0 + 8) * 128 + col] =
                    __floats2half2_rn(acc[mi][ni][2], acc[mi][ni][3]);
        }
    }
}

// ---------------- layer-3 SGEMM: g_hw40[M,40] = relu(g_agg)[M,128] @ W3[128,40] --
__global__ __launch_bounds__(256) void sgemm40_kernel(const float* __restrict__ B, int M)
{
    const float* A = (const float*)g_agg;
    float* C = g_hw40;
    __shared__ float As[16][128];
    __shared__ float Bs[16][40];

    int tid = threadIdx.x;
    int block_row = blockIdx.x * 128;
    int tr = tid >> 3;
    int tc = tid & 7;

    float acc[4][5] = {};

    for (int k0 = 0; k0 < HID_F; k0 += 16) {
        #pragma unroll
        for (int p = 0; p < 2; p++) {
            int i = tid + p * 256;
            int m = i >> 2;
            int kq = (i & 3) << 2;
            int gm = block_row + m;
            float4 av = make_float4(0.f, 0.f, 0.f, 0.f);
            if (gm < M) av = *(const float4*)&A[(size_t)gm * HID_F + k0 + kq];
            As[kq + 0][m] = fmaxf(av.x, 0.f);
            As[kq + 1][m] = fmaxf(av.y, 0.f);
            As[kq + 2][m] = fmaxf(av.z, 0.f);
            As[kq + 3][m] = fmaxf(av.w, 0.f);
        }
        if (tid < 160) {
            int k = tid / 10;
            int n4 = (tid % 10) * 4;
            *(float4*)&Bs[k][n4] = *(const float4*)&B[(size_t)(k0 + k) * OUT_F + n4];
        }
        __syncthreads();

        #pragma unroll
        for (int k = 0; k < 16; k++) {
            float4 a4 = *(const float4*)&As[k][tr * 4];
            float a[4] = {a4.x, a4.y, a4.z, a4.w};
            float b[5];
            #pragma unroll
            for (int j = 0; j < 5; j++) b[j] = Bs[k][tc * 5 + j];
            #pragma unroll
            for (int i = 0; i < 4; i++)
                #pragma unroll
                for (int j = 0; j < 5; j++)
                    acc[i][j] += a[i] * b[j];
        }
        __syncthreads();
    }

    #pragma unroll
    for (int i = 0; i < 4; i++) {
        int gm = block_row + tr * 4 + i;
        if (gm >= M) continue;
        #pragma unroll
        for (int j = 0; j < 5; j++)
            C[(size_t)gm * OUT_F + tc * 5 + j] = acc[i][j];
    }
}

// ---------------- aggregation (fp16 h, 128-wide): g_agg = A_norm*g_hwh + bias --
__global__ __launch_bounds__(256) void aggregate16_kernel(const float* __restrict__ bias)
{
    int warp = (blockIdx.x * blockDim.x + threadIdx.x) >> 5;
    int lane = threadIdx.x & 31;
    if (warp >= N_NODES) return;
    const uint2* HW = (const uint2*)g_hwh;      // 4 halves per uint2; 32 per row
    int beg = g_off[warp], end = g_off[warp + 1];
    float4 acc = make_float4(0.f, 0.f, 0.f, 0.f);

    #define ACC_EDGE(sv, wv) do {                                   \
        uint2 u_ = HW[(size_t)(sv) * 32 + lane];                    \
        float2 f01_ = __half22float2(*(__half2*)&u_.x);             \
        float2 f23_ = __half22float2(*(__half2*)&u_.y);             \
        acc.x += (wv) * f01_.x; acc.y += (wv) * f01_.y;             \
        acc.z += (wv) * f23_.x; acc.w += (wv) * f23_.y;             \
    } while (0)

    int j = beg;
    for (; j + 4 <= end; j += 4) {
        int   s0 = g_csrc[j],     s1 = g_csrc[j + 1], s2 = g_csrc[j + 2], s3 = g_csrc[j + 3];
        float w0 = g_cnorm[j],    w1 = g_cnorm[j + 1], w2 = g_cnorm[j + 2], w3 = g_cnorm[j + 3];
        ACC_EDGE(s0, w0); ACC_EDGE(s1, w1); ACC_EDGE(s2, w2); ACC_EDGE(s3, w3);
    }
    for (; j < end; j++) ACC_EDGE(g_csrc[j], g_cnorm[j]);
    #undef ACC_EDGE

    float di = g_dinv[warp];
    float sw = di * di;
    uint2 u = HW[(size_t)warp * 32 + lane];
    float2 f01 = __half22float2(*(__half2*)&u.x);
    float2 f23 = __half22float2(*(__half2*)&u.y);
    float4 b4 = ((const float4*)bias)[lane];
    acc.x += sw * f01.x + b4.x;
    acc.y += sw * f01.y + b4.y;
    acc.z += sw * f23.x + b4.z;
    acc.w += sw * f23.y + b4.w;
    ((float4*)g_agg)[(size_t)warp * 32 + lane] = acc;
}

// ---------------- aggregation (fp32, 40-wide, layer 3 -> d_out) ----------------
__global__ __launch_bounds__(256) void aggregate40_kernel(
    const float* __restrict__ bias, float* __restrict__ out)
{
    int warp = (blockIdx.x * blockDim.x + threadIdx.x) >> 5;
    int lane = threadIdx.x & 31;
    if (warp >= N_NODES) return;
    bool active = lane < 10;                    // 40 floats = 10 float4
    const float4* HW = (const float4*)g_hw40;
    int beg = g_off[warp], end = g_off[warp + 1];
    float4 acc = make_float4(0.f, 0.f, 0.f, 0.f);

    int j = beg;
    for (; j + 4 <= end; j += 4) {
        int   s0 = g_csrc[j],     s1 = g_csrc[j + 1], s2 = g_csrc[j + 2], s3 = g_csrc[j + 3];
        float w0 = g_cnorm[j],    w1 = g_cnorm[j + 1], w2 = g_cnorm[j + 2], w3 = g_cnorm[j + 3];
        if (active) {
            float4 v0 = HW[(size_t)s0 * 10 + lane];
            float4 v1 = HW[(size_t)s1 * 10 + lane];
            float4 v2 = HW[(size_t)s2 * 10 + lane];
            float4 v3 = HW[(size_t)s3 * 10 + lane];
            acc.x += w0 * v0.x; acc.y += w0 * v0.y; acc.z += w0 * v0.z; acc.w += w0 * v0.w;
            acc.x += w1 * v1.x; acc.y += w1 * v1.y; acc.z += w1 * v1.z; acc.w += w1 * v1.w;
            acc.x += w2 * v2.x; acc.y += w2 * v2.y; acc.z += w2 * v2.z; acc.w += w2 * v2.w;
            acc.x += w3 * v3.x; acc.y += w3 * v3.y; acc.z += w3 * v3.z; acc.w += w3 * v3.w;
        }
    }
    for (; j < end; j++) {
        int s = g_csrc[j];
        float w = g_cnorm[j];
        if (active) {
            float4 v = HW[(size_t)s * 10 + lane];
            acc.x += w * v.x; acc.y += w * v.y; acc.z += w * v.z; acc.w += w * v.w;
        }
    }
    if (active) {
        float di = g_dinv[warp];
        float sw = di * di;
        float4 v = HW[(size_t)warp * 10 + lane];
        float4 b4 = ((const float4*)bias)[lane];
        acc.x += sw * v.x + b4.x;
        acc.y += sw * v.y + b4.y;
        acc.z += sw * v.z + b4.z;
        acc.w += sw * v.w + b4.w;
        ((float4*)out)[(size_t)warp * 10 + lane] = acc;
    }
}

// ---------------- log_softmax over 40 cols, warp per row, in-place ----------------
__global__ __launch_bounds__(256) void logsoftmax_kernel(float* __restrict__ out) {
    int row = (blockIdx.x * blockDim.x + threadIdx.x) >> 5;
    int lane = threadIdx.x & 31;
    if (row >= N_NODES) return;
    float* p = out + (size_t)row * OUT_F;
    float x1 = p[lane];
    float x2 = (lane < OUT_F - 32) ? p[32 + lane] : -3.4e38f;
    float m = fmaxf(x1, x2);
    #pragma unroll
    for (int o = 16; o > 0; o >>= 1) m = fmaxf(m, __shfl_xor_sync(0xFFFFFFFFu, m, o));
    float s = __expf(x1 - m) + ((lane < OUT_F - 32) ? __expf(x2 - m) : 0.0f);
    #pragma unroll
    for (int o = 16; o > 0; o >>= 1) s += __shfl_xor_sync(0xFFFFFFFFu, s, o);
    float lse = m + __logf(s);
    p[lane] = x1 - lse;
    if (lane < OUT_F - 32) p[32 + lane] = x2 - lse;
}

// ---------------- launch ----------------
extern "C" void kernel_launch(void* const* d_in, const int* in_sizes, int n_in,
                              void* d_out, int out_size)
{
    const float* x  = (const float*)d_in[0];
    const void*  ei = d_in[1];
    const float* W1 = (const float*)d_in[2];
    const float* b1 = (const float*)d_in[3];
    const float* W2 = (const float*)d_in[4];
    const float* b2 = (const float*)d_in[5];
    const float* W3 = (const float*)d_in[6];
    const float* b3 = (const float*)d_in[7];
    float* out = (float*)d_out;

    const int TB = 256;
    int agg_grid = (N_NODES * 32 + TB - 1) / TB;
    int gemm_grid = (N_NODES + 127) / 128;

    // bgemm128 (layer 1, CSR-independent) sits at slot 4 for the ncu window.
    detect_kernel<<<1, 32>>>((const int*)ei);                          // 1
    zero_deg_kernel<<<(N_NODES + TB - 1) / TB, TB>>>();                // 2
    deg_kernel<<<(N_EDGES + TB - 1) / TB, TB>>>(ei);                   // 3
    bgemm128_kernel<<<gemm_grid, 256>>>(x, W1, N_NODES, IN_F, 0, 0);   // 4 (profiled)
    scan_p1_kernel<<<N_BLKS, SCAN_B>>>();                              // 5
    scan_p2_kernel<<<1, 256>>>();                                      // 6
    scan_p3_kernel<<<N_BLKS, SCAN_B>>>();                              // 7
    fill_kernel<<<(N_EDGES + TB - 1) / TB, TB>>>(ei);                  // 8

    aggregate16_kernel<<<agg_grid, TB>>>(b1);                          // 9
    bgemm128_kernel<<<gemm_grid, 256>>>(x, W2, N_NODES, HID_F, 1, 1);  // 10
    aggregate16_kernel<<<agg_grid, TB>>>(b2);                          // 11
    sgemm40_kernel<<<gemm_grid, 256>>>(W3, N_NODES);                   // 12
    aggregate40_kernel<<<agg_grid, TB>>>(b3, out);                     // 13
    logsoftmax_kernel<<<agg_grid, TB>>>(out);                          // 14
}

// round 8
// speedup vs baseline: 1.6595x; 1.1203x over previous
#include <cuda_runtime.h>
#include <cuda_bf16.h>
#include <cuda_fp16.h>
#include <cstdint>

#define N_NODES 50000
#define N_EDGES 1600000
#define IN_F    256
#define HID_F   128
#define OUT_F   40
#define SCAN_B  256
#define N_BLKS  ((N_NODES + SCAN_B - 1) / SCAN_B)   // 196

// ---------------- scratch (device globals; no allocs allowed) ----------------
__device__ int   g_is64;
__device__ int   g_degc[N_NODES];
__device__ float g_dinv[N_NODES];
__device__ int   g_off[N_NODES + 1];
__device__ int   g_cursor[N_NODES];
__device__ int   g_bsum[N_BLKS];
__device__ int   g_csrc[N_EDGES];
__device__ float g_cnorm[N_EDGES];
__device__ __align__(16) __half g_hwh [N_NODES * HID_F];  // fp16 h for gather
__device__ __align__(16) __half g_hw40[N_NODES * OUT_F];  // fp16 layer-3 h
__device__ __align__(16) float  g_agg[N_NODES * HID_F];

// ---------------- dtype detection: int64 vs int32 edge_index ----------------
__global__ void detect_kernel(const int* __restrict__ ei32) {
    if (threadIdx.x == 0 && blockIdx.x == 0) {
        int ok = 1;
        #pragma unroll 1
        for (int i = 0; i < 512; i++) {
            if (ei32[2 * i + 1] != 0) { ok = 0; break; }
        }
        g_is64 = ok;
    }
}

__device__ __forceinline__ int load_id(const void* ei, int idx) {
    if (g_is64) return (int)((const long long*)ei)[idx];
    return ((const int*)ei)[idx];
}

// ---------------- small prep kernels ----------------
__global__ void zero_deg_kernel() {
    int i = blockIdx.x * blockDim.x + threadIdx.x;
    if (i < N_NODES) g_degc[i] = 0;
}

__global__ void deg_kernel(const void* __restrict__ ei) {
    int e = blockIdx.x * blockDim.x + threadIdx.x;
    if (e < N_EDGES) {
        int d = load_id(ei, N_EDGES + e);
        if ((unsigned)d < (unsigned)N_NODES) atomicAdd(&g_degc[d], 1);
    }
}

// ---------------- 3-phase parallel exclusive scan over g_degc ----------------
__global__ __launch_bounds__(SCAN_B) void scan_p1_kernel() {
    __shared__ int s_ws[8];
    int t = threadIdx.x, lane = t & 31, w = t >> 5;
    int i = blockIdx.x * SCAN_B + t;
    int v = (i < N_NODES) ? g_degc[i] : 0;
    if (i < N_NODES) g_dinv[i] = rsqrtf((float)v + 1.0f);   // +1 self-loop
    int x = v;
    #pragma unroll
    for (int o = 1; o < 32; o <<= 1) {
        int y = __shfl_up_sync(0xFFFFFFFFu, x, o);
        if (lane >= o) x += y;
    }
    if (lane == 31) s_ws[w] = x;
    __syncthreads();
    if (w == 0 && lane < 8) {
        int s = s_ws[lane];
        #pragma unroll
        for (int o = 1; o < 8; o <<= 1) {
            int y = __shfl_up_sync(0xFFu, s, o);
            if (lane >= o) s += y;
        }
        s_ws[lane] = s;
    }
    __syncthreads();
    int base = (w == 0) ? 0 : s_ws[w - 1];
    int excl = x - v + base;
    if (i < N_NODES) g_off[i] = excl;
    if (t == SCAN_B - 1) g_bsum[blockIdx.x] = x + base;      // block total
}

__global__ __launch_bounds__(256) void scan_p2_kernel() {
    __shared__ int s_ws[8];
    int t = threadIdx.x, lane = t & 31, w = t >> 5;
    int v = (t < N_BLKS) ? g_bsum[t] : 0;
    int x = v;
    #pragma unroll
    for (int o = 1; o < 32; o <<= 1) {
        int y = __shfl_up_sync(0xFFFFFFFFu, x, o);
        if (lane >= o) x += y;
    }
    if (lane == 31) s_ws[w] = x;
    __syncthreads();
    if (w == 0 && lane < 8) {
        int s = s_ws[lane];
        #pragma unroll
        for (int o = 1; o < 8; o <<= 1) {
            int y = __shfl_up_sync(0xFFu, s, o);
            if (lane >= o) s += y;
        }
        s_ws[lane] = s;
    }
    __syncthreads();
    int base = (w == 0) ? 0 : s_ws[w - 1];
    int incl = x + base;
    if (t < N_BLKS) g_bsum[t] = incl - v;                    // exclusive
    if (t == N_BLKS - 1) g_off[N_NODES] = incl;              // grand total
}

__global__ __launch_bounds__(SCAN_B) void scan_p3_kernel() {
    int i = blockIdx.x * SCAN_B + threadIdx.x;
    if (i < N_NODES) {
        int o = g_off[i] + g_bsum[blockIdx.x];
        g_off[i] = o;
        g_cursor[i] = o;
    }
}

__global__ void fill_kernel(const void* __restrict__ ei) {
    int e = blockIdx.x * blockDim.x + threadIdx.x;
    if (e < N_EDGES) {
        int s = load_id(ei, e);
        int d = load_id(ei, N_EDGES + e);
        if ((unsigned)s < (unsigned)N_NODES && (unsigned)d < (unsigned)N_NODES) {
            int pos = atomicAdd(&g_cursor[d], 1);
            g_csrc[pos] = s;
            g_cnorm[pos] = g_dinv[s] * g_dinv[d];
        }
    }
}

// ---------------- TF32 helpers ----------------
__device__ __forceinline__ uint32_t f2tf32(float f) {
    uint32_t u;
    asm("cvt.rna.tf32.f32 %0, %1;" : "=r"(u) : "f"(f));
    return u;
}

// mma.sync m16n8k8 tf32 -> f32 accumulate
__device__ __forceinline__ void mma_tf32(
    float* d, const uint32_t* a, const uint32_t* b)
{
    asm volatile(
        "mma.sync.aligned.m16n8k8.row.col.f32.tf32.tf32.f32 "
        "{%0,%1,%2,%3}, {%4,%5,%6,%7}, {%8,%9}, {%0,%1,%2,%3};"
        : "+f"(d[0]), "+f"(d[1]), "+f"(d[2]), "+f"(d[3])
        : "r"(a[0]), "r"(a[1]), "r"(a[2]), "r"(a[3]), "r"(b[0]), "r"(b[1]));
}

// ---------------- TF32 tensor-core GEMM for N=128: g_hwh = op(A)[M,K] @ B ----
// Block tile 128x128, BK=32, 8 warps x (64x32) warp tiles, m16n8k8.
// smem stride 36 words => fragment bank = (4r+c) mod 32, conflict-free.
__global__ __launch_bounds__(256, 2) void tgemm128_kernel(
    const float* __restrict__ A_ext, const float* __restrict__ B,
    int M, int K, int reluA, int a_sel)
{
    const float* A = a_sel ? (const float*)g_agg : A_ext;
    __half* C = g_hwh;

    __shared__ uint32_t As[128 * 36];
    __shared__ uint32_t Bs[128 * 36];

    int tid  = threadIdx.x;
    int lane = tid & 31;
    int warp = tid >> 5;
    int r = lane >> 2, c = lane & 3;
    int m_base = (warp >> 2) * 64;      // 0 or 64
    int n_base = (warp & 3) * 32;       // 0,32,64,96
    int block_row = blockIdx.x * 128;

    float acc[4][4][4];
    #pragma unroll
    for (int i = 0; i < 4; i++)
        #pragma unroll
        for (int j = 0; j < 4; j++)
            #pragma unroll
            for (int q = 0; q < 4; q++) acc[i][j][q] = 0.f;

    int a_m[4], a_kq[4];
    #pragma unroll
    for (int j = 0; j < 4; j++) {
        int u = tid + 256 * j;
        a_m[j]  = u >> 3;       // 0..127
        a_kq[j] = u & 7;        // float4 index in 32-k tile
    }
    int b_n   = tid & 127;
    int b_kq0 = tid >> 7;       // 0 or 1; kq = b_kq0 + 2j

    float4 pa[4];
    float  pb[4][4];

    // prefetch tile 0
    #pragma unroll
    for (int j = 0; j < 4; j++) {
        int gm = block_row + a_m[j];
        pa[j] = (gm < M) ? *(const float4*)&A[(size_t)gm * K + a_kq[j] * 4]
                         : make_float4(0.f, 0.f, 0.f, 0.f);
        int kq = b_kq0 + 2 * j;
        #pragma unroll
        for (int i = 0; i < 4; i++)
            pb[j][i] = B[(size_t)(kq * 4 + i) * 128 + b_n];
    }

    for (int k0 = 0; k0 < K; k0 += 32) {
        __syncthreads();
        // store prefetched tile to smem (tf32-rounded)
        #pragma unroll
        for (int j = 0; j < 4; j++) {
            float v[4] = {pa[j].x, pa[j].y, pa[j].z, pa[j].w};
            if (reluA) {
                #pragma unroll
                for (int i = 0; i < 4; i++) v[i] = fmaxf(v[i], 0.f);
            }
            int base = a_m[j] * 36 + a_kq[j] * 4;
            #pragma unroll
            for (int i = 0; i < 4; i++) As[base + i] = f2tf32(v[i]);
        }
        #pragma unroll
        for (int j = 0; j < 4; j++) {
            int kq = b_kq0 + 2 * j;
            int base = b_n * 36 + kq * 4;
            #pragma unroll
            for (int i = 0; i < 4; i++) Bs[base + i] = f2tf32(pb[j][i]);
        }
        __syncthreads();

        // prefetch next tile
        if (k0 + 32 < K) {
            #pragma unroll
            for (int j = 0; j < 4; j++) {
                int gm = block_row + a_m[j];
                pa[j] = (gm < M) ? *(const float4*)&A[(size_t)gm * K + k0 + 32 + a_kq[j] * 4]
                                 : make_float4(0.f, 0.f, 0.f, 0.f);
                int kq = b_kq0 + 2 * j;
                #pragma unroll
                for (int i = 0; i < 4; i++)
                    pb[j][i] = B[(size_t)(k0 + 32 + kq * 4 + i) * 128 + b_n];
            }
        }

        // compute: 4 k8 substeps
        #pragma unroll
        for (int ks = 0; ks < 4; ks++) {
            int kc = ks * 8 + c;
            uint32_t bf[4][2];
            #pragma unroll
            for (int ni = 0; ni < 4; ni++) {
                int n = n_base + ni * 8 + r;
                bf[ni][0] = Bs[n * 36 + kc];
                bf[ni][1] = Bs[n * 36 + kc + 4];
            }
            #pragma unroll
            for (int mi = 0; mi < 4; mi++) {
                int m0 = (m_base + mi * 16 + r) * 36 + kc;
                int m1 = (m_base + mi * 16 + 8 + r) * 36 + kc;
                uint32_t af[4];
                af[0] = As[m0];     af[1] = As[m1];
                af[2] = As[m0 + 4]; af[3] = As[m1 + 4];
                #pragma unroll
                for (int ni = 0; ni < 4; ni++)
                    mma_tf32(acc[mi][ni], af, bf[ni]);
            }
        }
    }

    // epilogue: fp16 store
    #pragma unroll
    for (int mi = 0; mi < 4; mi++) {
        int gr0 = block_row + m_base + mi * 16 + r;
        #pragma unroll
        for (int ni = 0; ni < 4; ni++) {
            int col = n_base + ni * 8 + 2 * c;
            if (gr0 < M)
                *(__half2*)&C[(size_t)gr0 * 128 + col] =
                    __floats2half2_rn(acc[mi][ni][0], acc[mi][ni][1]);
            if (gr0 + 8 < M)
                *(__half2*)&C[(size_t)(gr0 + 8) * 128 + col] =
                    __floats2half2_rn(acc[mi][ni][2], acc[mi][ni][3]);
        }
    }
}

// ---------------- layer-3 SGEMM: g_hw40[M,40] = relu(g_agg)[M,128] @ W3 -------
__global__ __launch_bounds__(256) void sgemm40_kernel(const float* __restrict__ B, int M)
{
    const float* A = (const float*)g_agg;
    __half* C = g_hw40;
    __shared__ float As[16][128];
    __shared__ float Bs[16][40];

    int tid = threadIdx.x;
    int block_row = blockIdx.x * 128;
    int tr = tid >> 3;
    int tc = tid & 7;

    float acc[4][5] = {};

    for (int k0 = 0; k0 < HID_F; k0 += 16) {
        #pragma unroll
        for (int p = 0; p < 2; p++) {
            int i = tid + p * 256;
            int m = i >> 2;
            int kq = (i & 3) << 2;
            int gm = block_row + m;
            float4 av = make_float4(0.f, 0.f, 0.f, 0.f);
            if (gm < M) av = *(const float4*)&A[(size_t)gm * HID_F + k0 + kq];
            As[kq + 0][m] = fmaxf(av.x, 0.f);
            As[kq + 1][m] = fmaxf(av.y, 0.f);
            As[kq + 2][m] = fmaxf(av.z, 0.f);
            As[kq + 3][m] = fmaxf(av.w, 0.f);
        }
        if (tid < 160) {
            int k = tid / 10;
            int n4 = (tid % 10) * 4;
            *(float4*)&Bs[k][n4] = *(const float4*)&B[(size_t)(k0 + k) * OUT_F + n4];
        }
        __syncthreads();

        #pragma unroll
        for (int k = 0; k < 16; k++) {
            float4 a4 = *(const float4*)&As[k][tr * 4];
            float a[4] = {a4.x, a4.y, a4.z, a4.w};
            float b[5];
            #pragma unroll
            for (int j = 0; j < 5; j++) b[j] = Bs[k][tc * 5 + j];
            #pragma unroll
            for (int i = 0; i < 4; i++)
                #pragma unroll
                for (int j = 0; j < 5; j++)
                    acc[i][j] += a[i] * b[j];
        }
        __syncthreads();
    }

    #pragma unroll
    for (int i = 0; i < 4; i++) {
        int gm = block_row + tr * 4 + i;
        if (gm >= M) continue;
        #pragma unroll
        for (int j = 0; j < 5; j++)
            C[(size_t)gm * OUT_F + tc * 5 + j] = __float2half_rn(acc[i][j]);
    }
}

// ---------------- aggregation (fp16 h, 128-wide): g_agg = A_norm*g_hwh + bias --
__global__ __launch_bounds__(256) void aggregate16_kernel(const float* __restrict__ bias)
{
    int warp = (blockIdx.x * blockDim.x + threadIdx.x) >> 5;
    int lane = threadIdx.x & 31;
    if (warp >= N_NODES) return;
    const uint2* HW = (const uint2*)g_hwh;      // 4 halves per uint2; 32 per row
    int beg = g_off[warp], end = g_off[warp + 1];
    float4 acc = make_float4(0.f, 0.f, 0.f, 0.f);

    #define ACC_EDGE(sv, wv) do {                                   \
        uint2 u_ = HW[(size_t)(sv) * 32 + lane];                    \
        float2 f01_ = __half22float2(*(__half2*)&u_.x);             \
        float2 f23_ = __half22float2(*(__half2*)&u_.y);             \
        acc.x += (wv) * f01_.x; acc.y += (wv) * f01_.y;             \
        acc.z += (wv) * f23_.x; acc.w += (wv) * f23_.y;             \
    } while (0)

    int j = beg;
    for (; j + 4 <= end; j += 4) {
        int   s0 = g_csrc[j],     s1 = g_csrc[j + 1], s2 = g_csrc[j + 2], s3 = g_csrc[j + 3];
        float w0 = g_cnorm[j],    w1 = g_cnorm[j + 1], w2 = g_cnorm[j + 2], w3 = g_cnorm[j + 3];
        ACC_EDGE(s0, w0); ACC_EDGE(s1, w1); ACC_EDGE(s2, w2); ACC_EDGE(s3, w3);
    }
    for (; j < end; j++) ACC_EDGE(g_csrc[j], g_cnorm[j]);
    #undef ACC_EDGE

    float di = g_dinv[warp];
    float sw = di * di;
    uint2 u = HW[(size_t)warp * 32 + lane];
    float2 f01 = __half22float2(*(__half2*)&u.x);
    float2 f23 = __half22float2(*(__half2*)&u.y);
    float4 b4 = ((const float4*)bias)[lane];
    acc.x += sw * f01.x + b4.x;
    acc.y += sw * f01.y + b4.y;
    acc.z += sw * f23.x + b4.z;
    acc.w += sw * f23.y + b4.w;
    ((float4*)g_agg)[(size_t)warp * 32 + lane] = acc;
}

// ---------------- aggregation (fp16 h, 40-wide, layer 3 -> d_out fp32) --------
__global__ __launch_bounds__(256) void aggregate40_kernel(
    const float* __restrict__ bias, float* __restrict__ out)
{
    int warp = (blockIdx.x * blockDim.x + threadIdx.x) >> 5;
    int lane = threadIdx.x & 31;
    if (warp >= N_NODES) return;
    bool active = lane < 10;                    // 40 halves = 10 uint2
    const uint2* HW = (const uint2*)g_hw40;
    int beg = g_off[warp], end = g_off[warp + 1];
    float4 acc = make_float4(0.f, 0.f, 0.f, 0.f);

    #define ACC_E40(sv, wv) do {                                    \
        if (active) {                                               \
            uint2 u_ = HW[(size_t)(sv) * 10 + lane];                \
            float2 f01_ = __half22float2(*(__half2*)&u_.x);         \
            float2 f23_ = __half22float2(*(__half2*)&u_.y);         \
            acc.x += (wv) * f01_.x; acc.y += (wv) * f01_.y;         \
            acc.z += (wv) * f23_.x; acc.w += (wv) * f23_.y;         \
        }                                                           \
    } while (0)

    int j = beg;
    for (; j + 4 <= end; j += 4) {
        int   s0 = g_csrc[j],     s1 = g_csrc[j + 1], s2 = g_csrc[j + 2], s3 = g_csrc[j + 3];
        float w0 = g_cnorm[j],    w1 = g_cnorm[j + 1], w2 = g_cnorm[j + 2], w3 = g_cnorm[j + 3];
        ACC_E40(s0, w0); ACC_E40(s1, w1); ACC_E40(s2, w2); ACC_E40(s3, w3);
    }
    for (; j < end; j++) ACC_E40(g_csrc[j], g_cnorm[j]);
    #undef ACC_E40

    if (active) {
        float di = g_dinv[warp];
        float sw = di * di;
        uint2 u = HW[(size_t)warp * 10 + lane];
        float2 f01 = __half22float2(*(__half2*)&u.x);
        float2 f23 = __half22float2(*(__half2*)&u.y);
        float4 b4 = ((const float4*)bias)[lane];
        acc.x += sw * f01.x + b4.x;
        acc.y += sw * f01.y + b4.y;
        acc.z += sw * f23.x + b4.z;
        acc.w += sw * f23.y + b4.w;
        ((float4*)out)[(size_t)warp * 10 + lane] = acc;
    }
}

// ---------------- log_softmax over 40 cols, warp per row, in-place ----------------
__global__ __launch_bounds__(256) void logsoftmax_kernel(float* __restrict__ out) {
    int row = (blockIdx.x * blockDim.x + threadIdx.x) >> 5;
    int lane = threadIdx.x & 31;
    if (row >= N_NODES) return;
    float* p = out + (size_t)row * OUT_F;
    float x1 = p[lane];
    float x2 = (lane < OUT_F - 32) ? p[32 + lane] : -3.4e38f;
    float m = fmaxf(x1, x2);
    #pragma unroll
    for (int o = 16; o > 0; o >>= 1) m = fmaxf(m, __shfl_xor_sync(0xFFFFFFFFu, m, o));
    float s = __expf(x1 - m) + ((lane < OUT_F - 32) ? __expf(x2 - m) : 0.0f);
    #pragma unroll
    for (int o = 16; o > 0; o >>= 1) s += __shfl_xor_sync(0xFFFFFFFFu, s, o);
    float lse = m + __logf(s);
    p[lane] = x1 - lse;
    if (lane < OUT_F - 32) p[32 + lane] = x2 - lse;
}

// ---------------- launch ----------------
extern "C" void kernel_launch(void* const* d_in, const int* in_sizes, int n_in,
                              void* d_out, int out_size)
{
    const float* x  = (const float*)d_in[0];
    const void*  ei = d_in[1];
    const float* W1 = (const float*)d_in[2];
    const float* b1 = (const float*)d_in[3];
    const float* W2 = (const float*)d_in[4];
    const float* b2 = (const float*)d_in[5];
    const float* W3 = (const float*)d_in[6];
    const float* b3 = (const float*)d_in[7];
    float* out = (float*)d_out;

    const int TB = 256;
    int agg_grid = (N_NODES * 32 + TB - 1) / TB;
    int gemm_grid = (N_NODES + 127) / 128;

    // tgemm128 (layer 1, CSR-independent) sits at slot 4 for the ncu window.
    detect_kernel<<<1, 32>>>((const int*)ei);                          // 1
    zero_deg_kernel<<<(N_NODES + TB - 1) / TB, TB>>>();                // 2
    deg_kernel<<<(N_EDGES + TB - 1) / TB, TB>>>(ei);                   // 3
    tgemm128_kernel<<<gemm_grid, 256>>>(x, W1, N_NODES, IN_F, 0, 0);   // 4 (profiled)
    scan_p1_kernel<<<N_BLKS, SCAN_B>>>();                              // 5
    scan_p2_kernel<<<1, 256>>>();                                      // 6
    scan_p3_kernel<<<N_BLKS, SCAN_B>>>();                              // 7
    fill_kernel<<<(N_EDGES + TB - 1) / TB, TB>>>(ei);                  // 8

    aggregate16_kernel<<<agg_grid, TB>>>(b1);                          // 9
    tgemm128_kernel<<<gemm_grid, 256>>>(x, W2, N_NODES, HID_F, 1, 1);  // 10
    aggregate16_kernel<<<agg_grid, TB>>>(b2);                          // 11
    sgemm40_kernel<<<gemm_grid, 256>>>(W3, N_NODES);                   // 12
    aggregate40_kernel<<<agg_grid, TB>>>(b3, out);                     // 13
    logsoftmax_kernel<<<agg_grid, TB>>>(out);                          // 14
}

// round 9
// speedup vs baseline: 1.8378x; 1.1075x over previous
#include <cuda_runtime.h>
#include <cuda_bf16.h>
#include <cuda_fp16.h>
#include <cstdint>

#define N_NODES 50000
#define N_EDGES 1600000
#define IN_F    256
#define HID_F   128
#define OUT_F   40
#define SCAN_B  256
#define N_BLKS  ((N_NODES + SCAN_B - 1) / SCAN_B)   // 196

// ---------------- scratch (device globals; no allocs allowed) ----------------
__device__ int   g_is64;
__device__ int   g_degc[N_NODES];
__device__ float g_dinv[N_NODES];
__device__ int   g_off[N_NODES + 1];
__device__ int   g_cursor[N_NODES];
__device__ int   g_bsum[N_BLKS];
__device__ int   g_csrc[N_EDGES];
__device__ __align__(16) __half g_hwh [N_NODES * HID_F];  // fp16 dinv-scaled h
__device__ __align__(16) __half g_hw40[N_NODES * OUT_F];  // fp16 dinv-scaled layer-3 h
__device__ __align__(16) float  g_agg[N_NODES * HID_F];

// ---------------- init: zero degree counters + dtype detection ----------------
__global__ void init_kernel(const int* __restrict__ ei32) {
    int i = blockIdx.x * blockDim.x + threadIdx.x;
    if (i < N_NODES) g_degc[i] = 0;
    if (i == 0) {
        int ok = 1;
        #pragma unroll 1
        for (int k = 0; k < 512; k++) {
            if (ei32[2 * k + 1] != 0) { ok = 0; break; }
        }
        g_is64 = ok;
    }
}

__device__ __forceinline__ int load_id(const void* ei, int idx) {
    if (g_is64) return (int)((const long long*)ei)[idx];
    return ((const int*)ei)[idx];
}

__global__ void deg_kernel(const void* __restrict__ ei) {
    int e = blockIdx.x * blockDim.x + threadIdx.x;
    if (e < N_EDGES) {
        int d = load_id(ei, N_EDGES + e);
        if ((unsigned)d < (unsigned)N_NODES) atomicAdd(&g_degc[d], 1);
    }
}

// ---------------- 3-phase parallel exclusive scan over g_degc ----------------
__global__ __launch_bounds__(SCAN_B) void scan_p1_kernel() {
    __shared__ int s_ws[8];
    int t = threadIdx.x, lane = t & 31, w = t >> 5;
    int i = blockIdx.x * SCAN_B + t;
    int v = (i < N_NODES) ? g_degc[i] : 0;
    if (i < N_NODES) g_dinv[i] = rsqrtf((float)v + 1.0f);   // +1 self-loop
    int x = v;
    #pragma unroll
    for (int o = 1; o < 32; o <<= 1) {
        int y = __shfl_up_sync(0xFFFFFFFFu, x, o);
        if (lane >= o) x += y;
    }
    if (lane == 31) s_ws[w] = x;
    __syncthreads();
    if (w == 0 && lane < 8) {
        int s = s_ws[lane];
        #pragma unroll
        for (int o = 1; o < 8; o <<= 1) {
            int y = __shfl_up_sync(0xFFu, s, o);
            if (lane >= o) s += y;
        }
        s_ws[lane] = s;
    }
    __syncthreads();
    int base = (w == 0) ? 0 : s_ws[w - 1];
    int excl = x - v + base;
    if (i < N_NODES) g_off[i] = excl;
    if (t == SCAN_B - 1) g_bsum[blockIdx.x] = x + base;      // block total
}

__global__ __launch_bounds__(256) void scan_p2_kernel() {
    __shared__ int s_ws[8];
    int t = threadIdx.x, lane = t & 31, w = t >> 5;
    int v = (t < N_BLKS) ? g_bsum[t] : 0;
    int x = v;
    #pragma unroll
    for (int o = 1; o < 32; o <<= 1) {
        int y = __shfl_up_sync(0xFFFFFFFFu, x, o);
        if (lane >= o) x += y;
    }
    if (lane == 31) s_ws[w] = x;
    __syncthreads();
    if (w == 0 && lane < 8) {
        int s = s_ws[lane];
        #pragma unroll
        for (int o = 1; o < 8; o <<= 1) {
            int y = __shfl_up_sync(0xFFu, s, o);
            if (lane >= o) s += y;
        }
        s_ws[lane] = s;
    }
    __syncthreads();
    int base = (w == 0) ? 0 : s_ws[w - 1];
    int incl = x + base;
    if (t < N_BLKS) g_bsum[t] = incl - v;                    // exclusive
    if (t == N_BLKS - 1) g_off[N_NODES] = incl;              // grand total
}

__global__ __launch_bounds__(SCAN_B) void scan_p3_kernel() {
    int i = blockIdx.x * SCAN_B + threadIdx.x;
    if (i < N_NODES) {
        int o = g_off[i] + g_bsum[blockIdx.x];
        g_off[i] = o;
        g_cursor[i] = o;
    }
}

// fill: only src ids (norm weights are gone — folded into row scaling)
__global__ void fill_kernel(const void* __restrict__ ei) {
    int e = blockIdx.x * blockDim.x + threadIdx.x;
    if (e < N_EDGES) {
        int s = load_id(ei, e);
        int d = load_id(ei, N_EDGES + e);
        if ((unsigned)s < (unsigned)N_NODES && (unsigned)d < (unsigned)N_NODES) {
            int pos = atomicAdd(&g_cursor[d], 1);
            g_csrc[pos] = s;
        }
    }
}

// ---------------- TF32 helpers ----------------
__device__ __forceinline__ uint32_t f2tf32(float f) {
    uint32_t u;
    asm("cvt.rna.tf32.f32 %0, %1;" : "=r"(u) : "f"(f));
    return u;
}

__device__ __forceinline__ void mma_tf32(
    float* d, const uint32_t* a, const uint32_t* b)
{
    asm volatile(
        "mma.sync.aligned.m16n8k8.row.col.f32.tf32.tf32.f32 "
        "{%0,%1,%2,%3}, {%4,%5,%6,%7}, {%8,%9}, {%0,%1,%2,%3};"
        : "+f"(d[0]), "+f"(d[1]), "+f"(d[2]), "+f"(d[3])
        : "r"(a[0]), "r"(a[1]), "r"(a[2]), "r"(a[3]), "r"(b[0]), "r"(b[1]));
}

// ---------------- TF32 GEMM for N=128: g_hwh = dinv .* (A[M,K] @ B[K,128]) ---
// Epilogue scales row i by g_dinv[i] and stores fp16.
__global__ __launch_bounds__(256, 2) void tgemm128_kernel(
    const float* __restrict__ A_ext, const float* __restrict__ B,
    int M, int K, int a_sel)
{
    const float* A = a_sel ? (const float*)g_agg : A_ext;
    __half* C = g_hwh;

    __shared__ uint32_t As[128 * 36];
    __shared__ uint32_t Bs[128 * 36];

    int tid  = threadIdx.x;
    int lane = tid & 31;
    int warp = tid >> 5;
    int r = lane >> 2, c = lane & 3;
    int m_base = (warp >> 2) * 64;
    int n_base = (warp & 3) * 32;
    int block_row = blockIdx.x * 128;

    float acc[4][4][4];
    #pragma unroll
    for (int i = 0; i < 4; i++)
        #pragma unroll
        for (int j = 0; j < 4; j++)
            #pragma unroll
            for (int q = 0; q < 4; q++) acc[i][j][q] = 0.f;

    int a_m[4], a_kq[4];
    #pragma unroll
    for (int j = 0; j < 4; j++) {
        int u = tid + 256 * j;
        a_m[j]  = u >> 3;
        a_kq[j] = u & 7;
    }
    int b_n   = tid & 127;
    int b_kq0 = tid >> 7;

    float4 pa[4];
    float  pb[4][4];

    #pragma unroll
    for (int j = 0; j < 4; j++) {
        int gm = block_row + a_m[j];
        pa[j] = (gm < M) ? *(const float4*)&A[(size_t)gm * K + a_kq[j] * 4]
                         : make_float4(0.f, 0.f, 0.f, 0.f);
        int kq = b_kq0 + 2 * j;
        #pragma unroll
        for (int i = 0; i < 4; i++)
            pb[j][i] = B[(size_t)(kq * 4 + i) * 128 + b_n];
    }

    for (int k0 = 0; k0 < K; k0 += 32) {
        __syncthreads();
        #pragma unroll
        for (int j = 0; j < 4; j++) {
            int base = a_m[j] * 36 + a_kq[j] * 4;
            As[base + 0] = f2tf32(pa[j].x);
            As[base + 1] = f2tf32(pa[j].y);
            As[base + 2] = f2tf32(pa[j].z);
            As[base + 3] = f2tf32(pa[j].w);
        }
        #pragma unroll
        for (int j = 0; j < 4; j++) {
            int kq = b_kq0 + 2 * j;
            int base = b_n * 36 + kq * 4;
            #pragma unroll
            for (int i = 0; i < 4; i++) Bs[base + i] = f2tf32(pb[j][i]);
        }
        __syncthreads();

        if (k0 + 32 < K) {
            #pragma unroll
            for (int j = 0; j < 4; j++) {
                int gm = block_row + a_m[j];
                pa[j] = (gm < M) ? *(const float4*)&A[(size_t)gm * K + k0 + 32 + a_kq[j] * 4]
                                 : make_float4(0.f, 0.f, 0.f, 0.f);
                int kq = b_kq0 + 2 * j;
                #pragma unroll
                for (int i = 0; i < 4; i++)
                    pb[j][i] = B[(size_t)(k0 + 32 + kq * 4 + i) * 128 + b_n];
            }
        }

        #pragma unroll
        for (int ks = 0; ks < 4; ks++) {
            int kc = ks * 8 + c;
            uint32_t bf[4][2];
            #pragma unroll
            for (int ni = 0; ni < 4; ni++) {
                int n = n_base + ni * 8 + r;
                bf[ni][0] = Bs[n * 36 + kc];
                bf[ni][1] = Bs[n * 36 + kc + 4];
            }
            #pragma unroll
            for (int mi = 0; mi < 4; mi++) {
                int m0 = (m_base + mi * 16 + r) * 36 + kc;
                int m1 = (m_base + mi * 16 + 8 + r) * 36 + kc;
                uint32_t af[4];
                af[0] = As[m0];     af[1] = As[m1];
                af[2] = As[m0 + 4]; af[3] = As[m1 + 4];
                #pragma unroll
                for (int ni = 0; ni < 4; ni++)
                    mma_tf32(acc[mi][ni], af, bf[ni]);
            }
        }
    }

    // epilogue: scale rows by dinv, fp16 store
    #pragma unroll
    for (int mi = 0; mi < 4; mi++) {
        int gr0 = block_row + m_base + mi * 16 + r;
        float d0 = (gr0 < M)     ? g_dinv[gr0]     : 0.f;
        float d1 = (gr0 + 8 < M) ? g_dinv[gr0 + 8] : 0.f;
        #pragma unroll
        for (int ni = 0; ni < 4; ni++) {
            int col = n_base + ni * 8 + 2 * c;
            if (gr0 < M)
                *(__half2*)&C[(size_t)gr0 * 128 + col] =
                    __floats2half2_rn(acc[mi][ni][0] * d0, acc[mi][ni][1] * d0);
            if (gr0 + 8 < M)
                *(__half2*)&C[(size_t)(gr0 + 8) * 128 + col] =
                    __floats2half2_rn(acc[mi][ni][2] * d1, acc[mi][ni][3] * d1);
        }
    }
}

// ---------------- layer-3 SGEMM: g_hw40 = dinv .* (g_agg[M,128] @ W3[128,40]) -
__global__ __launch_bounds__(256) void sgemm40_kernel(const float* __restrict__ B, int M)
{
    const float* A = (const float*)g_agg;   // already relu'd by aggregate
    __half* C = g_hw40;
    __shared__ float As[16][128];
    __shared__ float Bs[16][40];

    int tid = threadIdx.x;
    int block_row = blockIdx.x * 128;
    int tr = tid >> 3;
    int tc = tid & 7;

    float acc[4][5] = {};

    for (int k0 = 0; k0 < HID_F; k0 += 16) {
        #pragma unroll
        for (int p = 0; p < 2; p++) {
            int i = tid + p * 256;
            int m = i >> 2;
            int kq = (i & 3) << 2;
            int gm = block_row + m;
            float4 av = make_float4(0.f, 0.f, 0.f, 0.f);
            if (gm < M) av = *(const float4*)&A[(size_t)gm * HID_F + k0 + kq];
            As[kq + 0][m] = av.x;
            As[kq + 1][m] = av.y;
            As[kq + 2][m] = av.z;
            As[kq + 3][m] = av.w;
        }
        if (tid < 160) {
            int k = tid / 10;
            int n4 = (tid % 10) * 4;
            *(float4*)&Bs[k][n4] = *(const float4*)&B[(size_t)(k0 + k) * OUT_F + n4];
        }
        __syncthreads();

        #pragma unroll
        for (int k = 0; k < 16; k++) {
            float4 a4 = *(const float4*)&As[k][tr * 4];
            float a[4] = {a4.x, a4.y, a4.z, a4.w};
            float b[5];
            #pragma unroll
            for (int j = 0; j < 5; j++) b[j] = Bs[k][tc * 5 + j];
            #pragma unroll
            for (int i = 0; i < 4; i++)
                #pragma unroll
                for (int j = 0; j < 5; j++)
                    acc[i][j] += a[i] * b[j];
        }
        __syncthreads();
    }

    #pragma unroll
    for (int i = 0; i < 4; i++) {
        int gm = block_row + tr * 4 + i;
        if (gm >= M) continue;
        float di = g_dinv[gm];
        #pragma unroll
        for (int j = 0; j < 5; j++)
            C[(size_t)gm * OUT_F + tc * 5 + j] = __float2half_rn(acc[i][j] * di);
    }
}

// ---- aggregation (fp16 scaled h, 128-wide): g_agg = relu(dinv.*(Σ+own) + b) --
__global__ __launch_bounds__(256) void aggregate16_kernel(const float* __restrict__ bias)
{
    int warp = (blockIdx.x * blockDim.x + threadIdx.x) >> 5;
    int lane = threadIdx.x & 31;
    if (warp >= N_NODES) return;
    const uint2* HW = (const uint2*)g_hwh;      // 4 halves per uint2; 32 per row
    int beg = g_off[warp], end = g_off[warp + 1];
    float4 acc = make_float4(0.f, 0.f, 0.f, 0.f);

    #define ACC_EDGE(sv) do {                                       \
        uint2 u_ = HW[(size_t)(sv) * 32 + lane];                    \
        float2 f01_ = __half22float2(*(__half2*)&u_.x);             \
        float2 f23_ = __half22float2(*(__half2*)&u_.y);             \
        acc.x += f01_.x; acc.y += f01_.y;                           \
        acc.z += f23_.x; acc.w += f23_.y;                           \
    } while (0)

    int j = beg;
    for (; j + 4 <= end; j += 4) {
        int s0 = g_csrc[j],     s1 = g_csrc[j + 1];
        int s2 = g_csrc[j + 2], s3 = g_csrc[j + 3];
        ACC_EDGE(s0); ACC_EDGE(s1); ACC_EDGE(s2); ACC_EDGE(s3);
    }
    for (; j < end; j++) ACC_EDGE(g_csrc[j]);
    #undef ACC_EDGE

    ACC_OWN: ;
    float di = g_dinv[warp];
    uint2 u = HW[(size_t)warp * 32 + lane];     // own scaled row (self-loop)
    float2 f01 = __half22float2(*(__half2*)&u.x);
    float2 f23 = __half22float2(*(__half2*)&u.y);
    float4 b4 = ((const float4*)bias)[lane];
    float4 res;
    res.x = fmaxf((acc.x + f01.x) * di + b4.x, 0.f);
    res.y = fmaxf((acc.y + f01.y) * di + b4.y, 0.f);
    res.z = fmaxf((acc.z + f23.x) * di + b4.z, 0.f);
    res.w = fmaxf((acc.w + f23.y) * di + b4.w, 0.f);
    ((float4*)g_agg)[(size_t)warp * 32 + lane] = res;
}

// ---- aggregation (40-wide) + fused log_softmax -> d_out ----------------------
__global__ __launch_bounds__(256) void aggregate40_lsm_kernel(
    const float* __restrict__ bias, float* __restrict__ out)
{
    int warp = (blockIdx.x * blockDim.x + threadIdx.x) >> 5;
    int lane = threadIdx.x & 31;
    if (warp >= N_NODES) return;
    bool active = lane < 10;                    // 40 halves = 10 uint2
    const uint2* HW = (const uint2*)g_hw40;
    int beg = g_off[warp], end = g_off[warp + 1];
    float4 acc = make_float4(0.f, 0.f, 0.f, 0.f);

    #define ACC_E40(sv) do {                                        \
        if (active) {                                               \
            uint2 u_ = HW[(size_t)(sv) * 10 + lane];                \
            float2 f01_ = __half22float2(*(__half2*)&u_.x);         \
            float2 f23_ = __half22float2(*(__half2*)&u_.y);         \
            acc.x += f01_.x; acc.y += f01_.y;                       \
            acc.z += f23_.x; acc.w += f23_.y;                       \
        }                                                           \
    } while (0)

    int j = beg;
    for (; j + 4 <= end; j += 4) {
        int s0 = g_csrc[j],     s1 = g_csrc[j + 1];
        int s2 = g_csrc[j + 2], s3 = g_csrc[j + 3];
        ACC_E40(s0); ACC_E40(s1); ACC_E40(s2); ACC_E40(s3);
    }
    for (; j < end; j++) ACC_E40(g_csrc[j]);
    #undef ACC_E40

    float4 v = make_float4(-3.4e38f, -3.4e38f, -3.4e38f, -3.4e38f);
    if (active) {
        float di = g_dinv[warp];
        uint2 u = HW[(size_t)warp * 10 + lane];
        float2 f01 = __half22float2(*(__half2*)&u.x);
        float2 f23 = __half22float2(*(__half2*)&u.y);
        float4 b4 = ((const float4*)bias)[lane];
        v.x = (acc.x + f01.x) * di + b4.x;
        v.y = (acc.y + f01.y) * di + b4.y;
        v.z = (acc.z + f23.x) * di + b4.z;
        v.w = (acc.w + f23.y) * di + b4.w;
    }

    // fused log_softmax over the 40 values held in lanes 0..9 (x4 each)
    float m = fmaxf(fmaxf(v.x, v.y), fmaxf(v.z, v.w));
    #pragma unroll
    for (int o = 16; o > 0; o >>= 1) m = fmaxf(m, __shfl_xor_sync(0xFFFFFFFFu, m, o));
    float s = 0.f;
    if (active)
        s = __expf(v.x - m) + __expf(v.y - m) + __expf(v.z - m) + __expf(v.w - m);
    #pragma unroll
    for (int o = 16; o > 0; o >>= 1) s += __shfl_xor_sync(0xFFFFFFFFu, s, o);
    float lse = m + __logf(s);

    if (active) {
        float4 r = make_float4(v.x - lse, v.y - lse, v.z - lse, v.w - lse);
        ((float4*)out)[(size_t)warp * 10 + lane] = r;
    }
}

// ---------------- launch ----------------
extern "C" void kernel_launch(void* const* d_in, const int* in_sizes, int n_in,
                              void* d_out, int out_size)
{
    const float* x  = (const float*)d_in[0];
    const void*  ei = d_in[1];
    const float* W1 = (const float*)d_in[2];
    const float* b1 = (const float*)d_in[3];
    const float* W2 = (const float*)d_in[4];
    const float* b2 = (const float*)d_in[5];
    const float* W3 = (const float*)d_in[6];
    const float* b3 = (const float*)d_in[7];
    float* out = (float*)d_out;

    const int TB = 256;
    int agg_grid = (N_NODES * 32 + TB - 1) / TB;
    int gemm_grid = (N_NODES + 127) / 128;

    init_kernel<<<N_BLKS, SCAN_B>>>((const int*)ei);                   // 1 (zero+detect)
    deg_kernel<<<(N_EDGES + TB - 1) / TB, TB>>>(ei);                   // 2
    scan_p1_kernel<<<N_BLKS, SCAN_B>>>();                              // 3 (dinv + scan)
    tgemm128_kernel<<<gemm_grid, 256>>>(x, W1, N_NODES, IN_F, 0);      // 4 (profiled)
    scan_p2_kernel<<<1, 256>>>();                                      // 5
    scan_p3_kernel<<<N_BLKS, SCAN_B>>>();                              // 6
    fill_kernel<<<(N_EDGES + TB - 1) / TB, TB>>>(ei);                  // 7

    aggregate16_kernel<<<agg_grid, TB>>>(b1);                          // 8
    tgemm128_kernel<<<gemm_grid, 256>>>(x, W2, N_NODES, HID_F, 1);     // 9
    aggregate16_kernel<<<agg_grid, TB>>>(b2);                          // 10
    sgemm40_kernel<<<gemm_grid, 256>>>(W3, N_NODES);                   // 11
    aggregate40_lsm_kernel<<<agg_grid, TB>>>(b3, out);                 // 12
}

// round 10
// speedup vs baseline: 1.9284x; 1.0493x over previous
#include <cuda_runtime.h>
#include <cuda_bf16.h>
#include <cuda_fp16.h>
#include <cstdint>

#define N_NODES 50000
#define N_EDGES 1600000
#define IN_F    256
#define HID_F   128
#define OUT_F   40
#define SCAN_B  256
#define N_BLKS  ((N_NODES + SCAN_B - 1) / SCAN_B)   // 196

// ---------------- scratch (device globals; no allocs allowed) ----------------
__device__ int   g_is64;
__device__ int   g_degc[N_NODES];
__device__ float g_dinv[N_NODES];
__device__ int   g_off[N_NODES + 1];
__device__ int   g_cursor[N_NODES];
__device__ int   g_bsum[N_BLKS];
__device__ int   g_csrc[N_EDGES];
__device__ __align__(16) __half g_hwh [N_NODES * HID_F];  // fp16 dinv-scaled h
__device__ __align__(16) __half g_hw40[N_NODES * OUT_F];  // fp16 dinv-scaled layer-3 h
__device__ __align__(16) float  g_agg[N_NODES * HID_F];

// ---------------- init: zero degree counters + dtype detection ----------------
__global__ void init_kernel(const int* __restrict__ ei32) {
    int i = blockIdx.x * blockDim.x + threadIdx.x;
    if (i < N_NODES) g_degc[i] = 0;
    if (i == 0) {
        int ok = 1;
        #pragma unroll 1
        for (int k = 0; k < 512; k++) {
            if (ei32[2 * k + 1] != 0) { ok = 0; break; }
        }
        g_is64 = ok;
    }
}

__device__ __forceinline__ int load_id(const void* ei, int idx) {
    if (g_is64) return (int)((const long long*)ei)[idx];
    return ((const int*)ei)[idx];
}

__global__ void deg_kernel(const void* __restrict__ ei) {
    int e = blockIdx.x * blockDim.x + threadIdx.x;
    if (e < N_EDGES) {
        int d = load_id(ei, N_EDGES + e);
        if ((unsigned)d < (unsigned)N_NODES) atomicAdd(&g_degc[d], 1);
    }
}

// ---------------- 3-phase parallel exclusive scan over g_degc ----------------
__global__ __launch_bounds__(SCAN_B) void scan_p1_kernel() {
    __shared__ int s_ws[8];
    int t = threadIdx.x, lane = t & 31, w = t >> 5;
    int i = blockIdx.x * SCAN_B + t;
    int v = (i < N_NODES) ? g_degc[i] : 0;
    if (i < N_NODES) g_dinv[i] = rsqrtf((float)v + 1.0f);   // +1 self-loop
    int x = v;
    #pragma unroll
    for (int o = 1; o < 32; o <<= 1) {
        int y = __shfl_up_sync(0xFFFFFFFFu, x, o);
        if (lane >= o) x += y;
    }
    if (lane == 31) s_ws[w] = x;
    __syncthreads();
    if (w == 0 && lane < 8) {
        int s = s_ws[lane];
        #pragma unroll
        for (int o = 1; o < 8; o <<= 1) {
            int y = __shfl_up_sync(0xFFu, s, o);
            if (lane >= o) s += y;
        }
        s_ws[lane] = s;
    }
    __syncthreads();
    int base = (w == 0) ? 0 : s_ws[w - 1];
    int excl = x - v + base;
    if (i < N_NODES) g_off[i] = excl;
    if (t == SCAN_B - 1) g_bsum[blockIdx.x] = x + base;      // block total
}

__global__ __launch_bounds__(256) void scan_p2_kernel() {
    __shared__ int s_ws[8];
    int t = threadIdx.x, lane = t & 31, w = t >> 5;
    int v = (t < N_BLKS) ? g_bsum[t] : 0;
    int x = v;
    #pragma unroll
    for (int o = 1; o < 32; o <<= 1) {
        int y = __shfl_up_sync(0xFFFFFFFFu, x, o);
        if (lane >= o) x += y;
    }
    if (lane == 31) s_ws[w] = x;
    __syncthreads();
    if (w == 0 && lane < 8) {
        int s = s_ws[lane];
        #pragma unroll
        for (int o = 1; o < 8; o <<= 1) {
            int y = __shfl_up_sync(0xFFu, s, o);
            if (lane >= o) s += y;
        }
        s_ws[lane] = s;
    }
    __syncthreads();
    int base = (w == 0) ? 0 : s_ws[w - 1];
    int incl = x + base;
    if (t < N_BLKS) g_bsum[t] = incl - v;                    // exclusive
    if (t == N_BLKS - 1) g_off[N_NODES] = incl;              // grand total
}

__global__ __launch_bounds__(SCAN_B) void scan_p3_kernel() {
    int i = blockIdx.x * SCAN_B + threadIdx.x;
    if (i < N_NODES) {
        int o = g_off[i] + g_bsum[blockIdx.x];
        g_off[i] = o;
        g_cursor[i] = o;
    }
}

// fill: only src ids (norm weights folded into row scaling)
__global__ void fill_kernel(const void* __restrict__ ei) {
    int e = blockIdx.x * blockDim.x + threadIdx.x;
    if (e < N_EDGES) {
        int s = load_id(ei, e);
        int d = load_id(ei, N_EDGES + e);
        if ((unsigned)s < (unsigned)N_NODES && (unsigned)d < (unsigned)N_NODES) {
            int pos = atomicAdd(&g_cursor[d], 1);
            g_csrc[pos] = s;
        }
    }
}

// ---------------- FP16 MMA helpers ----------------
// mma.sync m16n8k16 f16 -> f32 accumulate
__device__ __forceinline__ void mma_f16(
    float* d, const uint32_t* a, const uint32_t* b)
{
    asm volatile(
        "mma.sync.aligned.m16n8k16.row.col.f32.f16.f16.f32 "
        "{%0,%1,%2,%3}, {%4,%5,%6,%7}, {%8,%9}, {%0,%1,%2,%3};"
        : "+f"(d[0]), "+f"(d[1]), "+f"(d[2]), "+f"(d[3])
        : "r"(a[0]), "r"(a[1]), "r"(a[2]), "r"(a[3]), "r"(b[0]), "r"(b[1]));
}

__device__ __forceinline__ uint32_t pack_h2(float a, float b) {
    __half2 h = __floats2half2_rn(a, b);
    return *(uint32_t*)&h;
}

// ---------------- FP16 GEMM for N=128: g_hwh = dinv .* (A[M,K] @ B[K,128]) ---
// Block tile 128x128, BK=32, 8 warps x (64x32) warp tiles, m16n8k16.
// smem rows: 16 half2-pairs per 32-k tile, stride 20 => conflict-free LDS.
__global__ __launch_bounds__(256, 2) void hgemm128_kernel(
    const float* __restrict__ A_ext, const float* __restrict__ B,
    int M, int K, int a_sel)
{
    const float* A = a_sel ? (const float*)g_agg : A_ext;
    __half* C = g_hwh;

    __shared__ uint32_t As[128 * 20];
    __shared__ uint32_t Bs[128 * 20];

    int tid  = threadIdx.x;
    int lane = tid & 31;
    int warp = tid >> 5;
    int r = lane >> 2, c = lane & 3;
    int m_base = (warp >> 2) * 64;      // 0 or 64
    int n_base = (warp & 3) * 32;       // 0,32,64,96
    int block_row = blockIdx.x * 128;

    float acc[4][4][4];
    #pragma unroll
    for (int i = 0; i < 4; i++)
        #pragma unroll
        for (int j = 0; j < 4; j++)
            #pragma unroll
            for (int q = 0; q < 4; q++) acc[i][j][q] = 0.f;

    int a_m[4], a_kq[4];
    #pragma unroll
    for (int j = 0; j < 4; j++) {
        int u = tid + 256 * j;
        a_m[j]  = u >> 3;       // 0..127
        a_kq[j] = u & 7;        // float4 index in 32-k tile
    }
    int b_n   = tid & 127;
    int b_kq0 = tid >> 7;       // 0 or 1; kq = b_kq0 + 2j

    float4 pa[4];
    float  pb[4][4];

    // prefetch tile 0
    #pragma unroll
    for (int j = 0; j < 4; j++) {
        int gm = block_row + a_m[j];
        pa[j] = (gm < M) ? *(const float4*)&A[(size_t)gm * K + a_kq[j] * 4]
                         : make_float4(0.f, 0.f, 0.f, 0.f);
        int kq = b_kq0 + 2 * j;
        #pragma unroll
        for (int i = 0; i < 4; i++)
            pb[j][i] = B[(size_t)(kq * 4 + i) * 128 + b_n];
    }

    for (int k0 = 0; k0 < K; k0 += 32) {
        __syncthreads();
        // store prefetched tile to smem (fp16-packed)
        #pragma unroll
        for (int j = 0; j < 4; j++) {
            int base = a_m[j] * 20 + a_kq[j] * 2;
            As[base + 0] = pack_h2(pa[j].x, pa[j].y);
            As[base + 1] = pack_h2(pa[j].z, pa[j].w);
        }
        #pragma unroll
        for (int j = 0; j < 4; j++) {
            int kq = b_kq0 + 2 * j;
            int base = b_n * 20 + kq * 2;
            Bs[base + 0] = pack_h2(pb[j][0], pb[j][1]);
            Bs[base + 1] = pack_h2(pb[j][2], pb[j][3]);
        }
        __syncthreads();

        // prefetch next tile
        if (k0 + 32 < K) {
            #pragma unroll
            for (int j = 0; j < 4; j++) {
                int gm = block_row + a_m[j];
                pa[j] = (gm < M) ? *(const float4*)&A[(size_t)gm * K + k0 + 32 + a_kq[j] * 4]
                                 : make_float4(0.f, 0.f, 0.f, 0.f);
                int kq = b_kq0 + 2 * j;
                #pragma unroll
                for (int i = 0; i < 4; i++)
                    pb[j][i] = B[(size_t)(k0 + 32 + kq * 4 + i) * 128 + b_n];
            }
        }

        // compute: 2 k16 substeps
        #pragma unroll
        for (int kk = 0; kk < 2; kk++) {
            int p0 = kk * 8 + c;
            uint32_t bf[4][2];
            #pragma unroll
            for (int ni = 0; ni < 4; ni++) {
                int n = n_base + ni * 8 + r;
                bf[ni][0] = Bs[n * 20 + p0];
                bf[ni][1] = Bs[n * 20 + p0 + 4];
            }
            #pragma unroll
            for (int mi = 0; mi < 4; mi++) {
                int i0 = (m_base + mi * 16 + r) * 20 + p0;
                int i1 = (m_base + mi * 16 + 8 + r) * 20 + p0;
                uint32_t af[4];
                af[0] = As[i0];     af[1] = As[i1];
                af[2] = As[i0 + 4]; af[3] = As[i1 + 4];
                #pragma unroll
                for (int ni = 0; ni < 4; ni++)
                    mma_f16(acc[mi][ni], af, bf[ni]);
            }
        }
    }

    // epilogue: scale rows by dinv, fp16 store
    #pragma unroll
    for (int mi = 0; mi < 4; mi++) {
        int gr0 = block_row + m_base + mi * 16 + r;
        float d0 = (gr0 < M)     ? g_dinv[gr0]     : 0.f;
        float d1 = (gr0 + 8 < M) ? g_dinv[gr0 + 8] : 0.f;
        #pragma unroll
        for (int ni = 0; ni < 4; ni++) {
            int col = n_base + ni * 8 + 2 * c;
            if (gr0 < M)
                *(__half2*)&C[(size_t)gr0 * 128 + col] =
                    __floats2half2_rn(acc[mi][ni][0] * d0, acc[mi][ni][1] * d0);
            if (gr0 + 8 < M)
                *(__half2*)&C[(size_t)(gr0 + 8) * 128 + col] =
                    __floats2half2_rn(acc[mi][ni][2] * d1, acc[mi][ni][3] * d1);
        }
    }
}

// ---------------- layer-3 SGEMM: g_hw40 = dinv .* (g_agg[M,128] @ W3[128,40]) -
__global__ __launch_bounds__(256) void sgemm40_kernel(const float* __restrict__ B, int M)
{
    const float* A = (const float*)g_agg;   // already relu'd by aggregate
    __half* C = g_hw40;
    __shared__ float As[16][128];
    __shared__ float Bs[16][40];

    int tid = threadIdx.x;
    int block_row = blockIdx.x * 128;
    int tr = tid >> 3;
    int tc = tid & 7;

    float acc[4][5] = {};

    for (int k0 = 0; k0 < HID_F; k0 += 16) {
        #pragma unroll
        for (int p = 0; p < 2; p++) {
            int i = tid + p * 256;
            int m = i >> 2;
            int kq = (i & 3) << 2;
            int gm = block_row + m;
            float4 av = make_float4(0.f, 0.f, 0.f, 0.f);
            if (gm < M) av = *(const float4*)&A[(size_t)gm * HID_F + k0 + kq];
            As[kq + 0][m] = av.x;
            As[kq + 1][m] = av.y;
            As[kq + 2][m] = av.z;
            As[kq + 3][m] = av.w;
        }
        if (tid < 160) {
            int k = tid / 10;
            int n4 = (tid % 10) * 4;
            *(float4*)&Bs[k][n4] = *(const float4*)&B[(size_t)(k0 + k) * OUT_F + n4];
        }
        __syncthreads();

        #pragma unroll
        for (int k = 0; k < 16; k++) {
            float4 a4 = *(const float4*)&As[k][tr * 4];
            float a[4] = {a4.x, a4.y, a4.z, a4.w};
            float b[5];
            #pragma unroll
            for (int j = 0; j < 5; j++) b[j] = Bs[k][tc * 5 + j];
            #pragma unroll
            for (int i = 0; i < 4; i++)
                #pragma unroll
                for (int j = 0; j < 5; j++)
                    acc[i][j] += a[i] * b[j];
        }
        __syncthreads();
    }

    #pragma unroll
    for (int i = 0; i < 4; i++) {
        int gm = block_row + tr * 4 + i;
        if (gm >= M) continue;
        float di = g_dinv[gm];
        #pragma unroll
        for (int j = 0; j < 5; j++)
            C[(size_t)gm * OUT_F + tc * 5 + j] = __float2half_rn(acc[i][j] * di);
    }
}

// ---- aggregation (fp16 scaled h, 128-wide): g_agg = relu(dinv.*(Σ+own) + b) --
__global__ __launch_bounds__(256) void aggregate16_kernel(const float* __restrict__ bias)
{
    int warp = (blockIdx.x * blockDim.x + threadIdx.x) >> 5;
    int lane = threadIdx.x & 31;
    if (warp >= N_NODES) return;
    const uint2* HW = (const uint2*)g_hwh;      // 4 halves per uint2; 32 per row
    int beg = g_off[warp], end = g_off[warp + 1];
    float4 acc = make_float4(0.f, 0.f, 0.f, 0.f);

    #define ACC_EDGE(sv) do {                                       \
        uint2 u_ = HW[(size_t)(sv) * 32 + lane];                    \
        float2 f01_ = __half22float2(*(__half2*)&u_.x);             \
        float2 f23_ = __half22float2(*(__half2*)&u_.y);             \
        acc.x += f01_.x; acc.y += f01_.y;                           \
        acc.z += f23_.x; acc.w += f23_.y;                           \
    } while (0)

    int j = beg;
    for (; j + 4 <= end; j += 4) {
        int s0 = g_csrc[j],     s1 = g_csrc[j + 1];
        int s2 = g_csrc[j + 2], s3 = g_csrc[j + 3];
        ACC_EDGE(s0); ACC_EDGE(s1); ACC_EDGE(s2); ACC_EDGE(s3);
    }
    for (; j < end; j++) ACC_EDGE(g_csrc[j]);
    #undef ACC_EDGE

    float di = g_dinv[warp];
    uint2 u = HW[(size_t)warp * 32 + lane];     // own scaled row (self-loop)
    float2 f01 = __half22float2(*(__half2*)&u.x);
    float2 f23 = __half22float2(*(__half2*)&u.y);
    float4 b4 = ((const float4*)bias)[lane];
    float4 res;
    res.x = fmaxf((acc.x + f01.x) * di + b4.x, 0.f);
    res.y = fmaxf((acc.y + f01.y) * di + b4.y, 0.f);
    res.z = fmaxf((acc.z + f23.x) * di + b4.z, 0.f);
    res.w = fmaxf((acc.w + f23.y) * di + b4.w, 0.f);
    ((float4*)g_agg)[(size_t)warp * 32 + lane] = res;
}

// ---- aggregation (40-wide) + fused log_softmax -> d_out ----------------------
__global__ __launch_bounds__(256) void aggregate40_lsm_kernel(
    const float* __restrict__ bias, float* __restrict__ out)
{
    int warp = (blockIdx.x * blockDim.x + threadIdx.x) >> 5;
    int lane = threadIdx.x & 31;
    if (warp >= N_NODES) return;
    bool active = lane < 10;                    // 40 halves = 10 uint2
    const uint2* HW = (const uint2*)g_hw40;
    int beg = g_off[warp], end = g_off[warp + 1];
    float4 acc = make_float4(0.f, 0.f, 0.f, 0.f);

    #define ACC_E40(sv) do {                                        \
        if (active) {                                               \
            uint2 u_ = HW[(size_t)(sv) * 10 + lane];                \
            float2 f01_ = __half22float2(*(__half2*)&u_.x);         \
            float2 f23_ = __half22float2(*(__half2*)&u_.y);         \
            acc.x += f01_.x; acc.y += f01_.y;                       \
            acc.z += f23_.x; acc.w += f23_.y;                       \
        }                                                           \
    } while (0)

    int j = beg;
    for (; j + 4 <= end; j += 4) {
        int s0 = g_csrc[j],     s1 = g_csrc[j + 1];
        int s2 = g_csrc[j + 2], s3 = g_csrc[j + 3];
        ACC_E40(s0); ACC_E40(s1); ACC_E40(s2); ACC_E40(s3);
    }
    for (; j < end; j++) ACC_E40(g_csrc[j]);
    #undef ACC_E40

    float4 v = make_float4(-3.4e38f, -3.4e38f, -3.4e38f, -3.4e38f);
    if (active) {
        float di = g_dinv[warp];
        uint2 u = HW[(size_t)warp * 10 + lane];
        float2 f01 = __half22float2(*(__half2*)&u.x);
        float2 f23 = __half22float2(*(__half2*)&u.y);
        float4 b4 = ((const float4*)bias)[lane];
        v.x = (acc.x + f01.x) * di + b4.x;
        v.y = (acc.y + f01.y) * di + b4.y;
        v.z = (acc.z + f23.x) * di + b4.z;
        v.w = (acc.w + f23.y) * di + b4.w;
    }

    // fused log_softmax over the 40 values held in lanes 0..9 (x4 each)
    float m = fmaxf(fmaxf(v.x, v.y), fmaxf(v.z, v.w));
    #pragma unroll
    for (int o = 16; o > 0; o >>= 1) m = fmaxf(m, __shfl_xor_sync(0xFFFFFFFFu, m, o));
    float s = 0.f;
    if (active)
        s = __expf(v.x - m) + __expf(v.y - m) + __expf(v.z - m) + __expf(v.w - m);
    #pragma unroll
    for (int o = 16; o > 0; o >>= 1) s += __shfl_xor_sync(0xFFFFFFFFu, s, o);
    float lse = m + __logf(s);

    if (active) {
        float4 r = make_float4(v.x - lse, v.y - lse, v.z - lse, v.w - lse);
        ((float4*)out)[(size_t)warp * 10 + lane] = r;
    }
}

// ---------------- launch ----------------
extern "C" void kernel_launch(void* const* d_in, const int* in_sizes, int n_in,
                              void* d_out, int out_size)
{
    const float* x  = (const float*)d_in[0];
    const void*  ei = d_in[1];
    const float* W1 = (const float*)d_in[2];
    const float* b1 = (const float*)d_in[3];
    const float* W2 = (const float*)d_in[4];
    const float* b2 = (const float*)d_in[5];
    const float* W3 = (const float*)d_in[6];
    const float* b3 = (const float*)d_in[7];
    float* out = (float*)d_out;

    const int TB = 256;
    int agg_grid = (N_NODES * 32 + TB - 1) / TB;
    int gemm_grid = (N_NODES + 127) / 128;

    init_kernel<<<N_BLKS, SCAN_B>>>((const int*)ei);                   // 1 (zero+detect)
    deg_kernel<<<(N_EDGES + TB - 1) / TB, TB>>>(ei);                   // 2
    scan_p1_kernel<<<N_BLKS, SCAN_B>>>();                              // 3 (dinv + scan)
    hgemm128_kernel<<<gemm_grid, 256>>>(x, W1, N_NODES, IN_F, 0);      // 4 (profiled)
    scan_p2_kernel<<<1, 256>>>();                                      // 5
    scan_p3_kernel<<<N_BLKS, SCAN_B>>>();                              // 6
    fill_kernel<<<(N_EDGES + TB - 1) / TB, TB>>>(ei);                  // 7

    aggregate16_kernel<<<agg_grid, TB>>>(b1);                          // 8
    hgemm128_kernel<<<gemm_grid, 256>>>(x, W2, N_NODES, HID_F, 1);     // 9
    aggregate16_kernel<<<agg_grid, TB>>>(b2);                          // 10
    sgemm40_kernel<<<gemm_grid, 256>>>(W3, N_NODES);                   // 11
    aggregate40_lsm_kernel<<<agg_grid, TB>>>(b3, out);                 // 12
}